// round 5
// baseline (speedup 1.0000x reference)
#include <cuda_runtime.h>
#include <cuda_bf16.h>

// Problem dims (fixed by the reference)
#define Bdim  8
#define Sdim  1024
#define Ddim  1024
#define Hdim  16
#define DKdim 64
#define Mdim  (Bdim * Sdim)   // 8192 rows

// ---------------------------------------------------------------------------
// Scratch: __device__ globals (no cudaMalloc allowed). 4 x 32 MB.
// ---------------------------------------------------------------------------
__device__ float g_q  [(size_t)Mdim * Ddim];
__device__ float g_k  [(size_t)Mdim * Ddim];
__device__ float g_v  [(size_t)Mdim * Ddim];
__device__ float g_att[(size_t)Mdim * Ddim];

// ---------------------------------------------------------------------------
// SGEMM with bias: C[M,N] = A[M,K] * B[K,N] + bias[N]
// 128x128 tile, BK=16, 256 threads, 8x8 per-thread microtile.
// ---------------------------------------------------------------------------
#define BM 128
#define BN 128
#define BK 16
#define TM 8
#define TN 8

__global__ __launch_bounds__(256) void sgemm_bias(
    const float* __restrict__ A, const float* __restrict__ Bm,
    const float* __restrict__ bias, float* __restrict__ C,
    int M, int N, int K)
{
    __shared__ float As[BK][BM + 4];   // transposed A tile; stride 132 floats (16B aligned)
    __shared__ float Bs[BK][BN];

    const int tid  = threadIdx.x;
    const int tx   = tid & 15;
    const int ty   = tid >> 4;
    const int brow = blockIdx.y * BM;
    const int bcol = blockIdx.x * BN;

    float acc[TM][TN];
#pragma unroll
    for (int i = 0; i < TM; i++)
#pragma unroll
        for (int j = 0; j < TN; j++) acc[i][j] = 0.f;

    for (int k0 = 0; k0 < K; k0 += BK) {
        // Load A tile (128 x 16) -> As transposed. 512 float4, 2 per thread.
#pragma unroll
        for (int i = 0; i < 2; i++) {
            int idx = tid + i * 256;
            int r   = idx >> 2;    // tile row 0..127
            int c4  = idx & 3;     // float4 column 0..3
            float4 v = *(const float4*)(A + (size_t)(brow + r) * K + k0 + c4 * 4);
            As[c4 * 4 + 0][r] = v.x;
            As[c4 * 4 + 1][r] = v.y;
            As[c4 * 4 + 2][r] = v.z;
            As[c4 * 4 + 3][r] = v.w;
        }
        // Load B tile (16 x 128). 512 float4, 2 per thread.
#pragma unroll
        for (int i = 0; i < 2; i++) {
            int idx = tid + i * 256;
            int r   = idx >> 5;    // 0..15
            int c4  = idx & 31;    // 0..31
            *(float4*)&Bs[r][c4 * 4] =
                *(const float4*)(Bm + (size_t)(k0 + r) * N + bcol + c4 * 4);
        }
        __syncthreads();

#pragma unroll
        for (int kk = 0; kk < BK; kk++) {
            float a[TM], b[TN];
#pragma unroll
            for (int i = 0; i < TM; i++) a[i] = As[kk][ty * TM + i];
#pragma unroll
            for (int j = 0; j < TN; j++) b[j] = Bs[kk][tx * TN + j];
#pragma unroll
            for (int i = 0; i < TM; i++)
#pragma unroll
                for (int j = 0; j < TN; j++) acc[i][j] += a[i] * b[j];
        }
        __syncthreads();
    }

    // Epilogue: add bias, vectorized store.
#pragma unroll
    for (int i = 0; i < TM; i++) {
        int r = brow + ty * TM + i;
#pragma unroll
        for (int j = 0; j < TN; j += 4) {
            int c = bcol + tx * TN + j;
            float4 o;
            o.x = acc[i][j + 0] + bias[c + 0];
            o.y = acc[i][j + 1] + bias[c + 1];
            o.z = acc[i][j + 2] + bias[c + 2];
            o.w = acc[i][j + 3] + bias[c + 3];
            *(float4*)(C + (size_t)r * N + c) = o;
        }
    }
}

// ---------------------------------------------------------------------------
// Flash-style attention.
// Grid: (S/64, H, B). Block: 256 threads (16x16 logical grid).
// Each block: 64 queries for one (b,h); loops over 32-key tiles with
// online softmax. Q,K held d-major in smem, P held k-major, so the two
// FMA loops have broadcast / low-conflict smem access.
// ---------------------------------------------------------------------------
__global__ __launch_bounds__(256) void attn_kernel(
    const float* __restrict__ Q, const float* __restrict__ K,
    const float* __restrict__ V, const int* __restrict__ masks,
    float* __restrict__ O)
{
    __shared__ float Qts[DKdim][64 + 1];   // [d][q], pre-scaled by 1/sqrt(DK)
    __shared__ float Kts[DKdim][32 + 1];   // [d][k]
    __shared__ float Vs [32][DKdim + 1];   // [k][d]
    __shared__ float Pts[32][64 + 1];      // [k][q]
    __shared__ int   msk[32];

    const int tid = threadIdx.x;
    const int tx  = tid & 15;   // covers 32 keys (x2) in QK^T, 64 dims (x4) in PV
    const int ty  = tid >> 4;   // covers 64 queries (x4)
    const int b   = blockIdx.z, h = blockIdx.y;
    const int q0  = blockIdx.x * 64;

    const float* Qb = Q + ((size_t)(b * Sdim + q0)) * Ddim + h * DKdim;
    const float* Kb = K + ((size_t)b * Sdim) * Ddim + h * DKdim;
    const float* Vb = V + ((size_t)b * Sdim) * Ddim + h * DKdim;

    // Load Q tile (64 x 64), pre-scaled. 1024 float4, 4 per thread.
#pragma unroll
    for (int i = 0; i < 4; i++) {
        int idx = tid + i * 256;
        int q   = idx >> 4;    // 0..63
        int dv  = idx & 15;    // 0..15
        float4 v = *(const float4*)(Qb + (size_t)q * Ddim + dv * 4);
        Qts[dv * 4 + 0][q] = v.x * 0.125f;
        Qts[dv * 4 + 1][q] = v.y * 0.125f;
        Qts[dv * 4 + 2][q] = v.z * 0.125f;
        Qts[dv * 4 + 3][q] = v.w * 0.125f;
    }

    float m_i[4], l_i[4], o[4][4];
#pragma unroll
    for (int i = 0; i < 4; i++) {
        m_i[i] = -1e30f;
        l_i[i] = 0.f;
#pragma unroll
        for (int j = 0; j < 4; j++) o[i][j] = 0.f;
    }

    for (int t = 0; t < Sdim / 32; t++) {
        const int kb = t * 32;
        __syncthreads();   // protect Kts/Vs/Pts before reload

        // Load K and V tiles (32 x 64 each). 512 float4, 2 per thread.
#pragma unroll
        for (int i = 0; i < 2; i++) {
            int idx = tid + i * 256;
            int k   = idx >> 4;    // 0..31
            int dv  = idx & 15;    // 0..15
            float4 kv = *(const float4*)(Kb + (size_t)(kb + k) * Ddim + dv * 4);
            Kts[dv * 4 + 0][k] = kv.x;
            Kts[dv * 4 + 1][k] = kv.y;
            Kts[dv * 4 + 2][k] = kv.z;
            Kts[dv * 4 + 3][k] = kv.w;
            float4 vv = *(const float4*)(Vb + (size_t)(kb + k) * Ddim + dv * 4);
            Vs[k][dv * 4 + 0] = vv.x;
            Vs[k][dv * 4 + 1] = vv.y;
            Vs[k][dv * 4 + 2] = vv.z;
            Vs[k][dv * 4 + 3] = vv.w;
        }
        if (tid < 32) msk[tid] = masks[b * Sdim + kb + tid];
        __syncthreads();

        // Scores: s[4 queries][2 keys]
        float s[4][2] = {{0.f, 0.f}, {0.f, 0.f}, {0.f, 0.f}, {0.f, 0.f}};
#pragma unroll 8
        for (int d = 0; d < DKdim; d++) {
            float a0 = Qts[d][ty * 4 + 0];
            float a1 = Qts[d][ty * 4 + 1];
            float a2 = Qts[d][ty * 4 + 2];
            float a3 = Qts[d][ty * 4 + 3];
            float b0 = Kts[d][tx * 2 + 0];
            float b1 = Kts[d][tx * 2 + 1];
            s[0][0] += a0 * b0;  s[0][1] += a0 * b1;
            s[1][0] += a1 * b0;  s[1][1] += a1 * b1;
            s[2][0] += a2 * b0;  s[2][1] += a2 * b1;
            s[3][0] += a3 * b0;  s[3][1] += a3 * b1;
        }
        // Mask (applied to logits)
#pragma unroll
        for (int j = 0; j < 2; j++) {
            if (msk[tx * 2 + j] == 0) {
#pragma unroll
                for (int i = 0; i < 4; i++) s[i][j] = -1e9f;
            }
        }

        // Online softmax update per query row (16 tx lanes share a row)
#pragma unroll
        for (int i = 0; i < 4; i++) {
            float tmax = fmaxf(s[i][0], s[i][1]);
#pragma unroll
            for (int off = 8; off; off >>= 1)
                tmax = fmaxf(tmax, __shfl_xor_sync(0xffffffffu, tmax, off));
            float nm   = fmaxf(m_i[i], tmax);
            float corr = __expf(m_i[i] - nm);
            float p0   = __expf(s[i][0] - nm);
            float p1   = __expf(s[i][1] - nm);
            float ts   = p0 + p1;
#pragma unroll
            for (int off = 8; off; off >>= 1)
                ts += __shfl_xor_sync(0xffffffffu, ts, off);
            l_i[i] = l_i[i] * corr + ts;
            m_i[i] = nm;
#pragma unroll
            for (int j = 0; j < 4; j++) o[i][j] *= corr;
            Pts[tx * 2 + 0][ty * 4 + i] = p0;
            Pts[tx * 2 + 1][ty * 4 + i] = p1;
        }
        __syncthreads();

        // O += P * V : o[4 queries][4 dims], dims d0 = tx*4
#pragma unroll 8
        for (int k = 0; k < 32; k++) {
            float a0 = Pts[k][ty * 4 + 0];
            float a1 = Pts[k][ty * 4 + 1];
            float a2 = Pts[k][ty * 4 + 2];
            float a3 = Pts[k][ty * 4 + 3];
            float b0 = Vs[k][tx * 4 + 0];
            float b1 = Vs[k][tx * 4 + 1];
            float b2 = Vs[k][tx * 4 + 2];
            float b3 = Vs[k][tx * 4 + 3];
            o[0][0] += a0 * b0;  o[0][1] += a0 * b1;  o[0][2] += a0 * b2;  o[0][3] += a0 * b3;
            o[1][0] += a1 * b0;  o[1][1] += a1 * b1;  o[1][2] += a1 * b2;  o[1][3] += a1 * b3;
            o[2][0] += a2 * b0;  o[2][1] += a2 * b1;  o[2][2] += a2 * b2;  o[2][3] += a2 * b3;
            o[3][0] += a3 * b0;  o[3][1] += a3 * b1;  o[3][2] += a3 * b2;  o[3][3] += a3 * b3;
        }
    }

    // Normalize + write: out[b, q, h*64 + d]
#pragma unroll
    for (int i = 0; i < 4; i++) {
        float inv = 1.0f / l_i[i];
        float4 r;
        r.x = o[i][0] * inv;
        r.y = o[i][1] * inv;
        r.z = o[i][2] * inv;
        r.w = o[i][3] * inv;
        *(float4*)(O + ((size_t)(b * Sdim + q0 + ty * 4 + i)) * Ddim
                     + h * DKdim + tx * 4) = r;
    }
}

// ---------------------------------------------------------------------------
// kernel_launch: 5 plain launches, graph-capturable, allocation-free.
// Input order (metadata): x, masks, Wq, bq, Wk, bk, Wv, bv, Wo, bo
// ---------------------------------------------------------------------------
extern "C" void kernel_launch(void* const* d_in, const int* in_sizes, int n_in,
                              void* d_out, int out_size)
{
    const float* x     = (const float*)d_in[0];
    const int*   masks = (const int*)  d_in[1];
    const float* Wq    = (const float*)d_in[2];
    const float* bq    = (const float*)d_in[3];
    const float* Wk    = (const float*)d_in[4];
    const float* bk    = (const float*)d_in[5];
    const float* Wv    = (const float*)d_in[6];
    const float* bv    = (const float*)d_in[7];
    const float* Wo    = (const float*)d_in[8];
    const float* bo    = (const float*)d_in[9];
    float* out = (float*)d_out;

    float *q, *k, *v, *att;
    cudaGetSymbolAddress((void**)&q,   g_q);
    cudaGetSymbolAddress((void**)&k,   g_k);
    cudaGetSymbolAddress((void**)&v,   g_v);
    cudaGetSymbolAddress((void**)&att, g_att);

    dim3 gg(Ddim / BN, Mdim / BM);   // (8, 64)
    sgemm_bias<<<gg, 256>>>(x, Wq, bq, q, Mdim, Ddim, Ddim);
    sgemm_bias<<<gg, 256>>>(x, Wk, bk, k, Mdim, Ddim, Ddim);
    sgemm_bias<<<gg, 256>>>(x, Wv, bv, v, Mdim, Ddim, Ddim);

    dim3 ga(Sdim / 64, Hdim, Bdim);  // (16, 16, 8)
    attn_kernel<<<ga, 256>>>(q, k, v, masks, att);

    sgemm_bias<<<gg, 256>>>(att, Wo, bo, out, Mdim, Ddim, Ddim);
}

// round 9
// speedup vs baseline: 1.5509x; 1.5509x over previous
#include <cuda_runtime.h>
#include <cuda_bf16.h>
#include <cstdint>

// Problem dims (fixed by the reference)
#define Bdim  8
#define Sdim  1024
#define Ddim  1024
#define Hdim  16
#define DKdim 64
#define Mdim  (Bdim * Sdim)   // 8192 rows
#define K2    2048            // split-K width (hi | lo)

// ---------------------------------------------------------------------------
// Scratch (__device__ globals; no cudaMalloc allowed)
// ---------------------------------------------------------------------------
__device__ __nv_bfloat16 g_xs  [(size_t)Mdim * K2];   // x  split   [M,2048]
__device__ __nv_bfloat16 g_wq  [(size_t)Ddim * K2];   // Wq^T split [N,2048]
__device__ __nv_bfloat16 g_wk  [(size_t)Ddim * K2];
__device__ __nv_bfloat16 g_wv  [(size_t)Ddim * K2];
__device__ __nv_bfloat16 g_wo  [(size_t)Ddim * K2];
__device__ float         g_q   [(size_t)Mdim * Ddim];
__device__ float         g_k   [(size_t)Mdim * Ddim];
__device__ float         g_v   [(size_t)Mdim * Ddim];
__device__ __nv_bfloat16 g_attb[(size_t)Mdim * K2];   // attn out split [M,2048]

// ---------------------------------------------------------------------------
// Helpers (arch-agnostic PTX only: cp.async, ldmatrix, mma.sync)
// ---------------------------------------------------------------------------
__device__ __forceinline__ uint32_t smem_u32(const void* p) {
    uint32_t a;
    asm("{ .reg .u64 t; cvta.to.shared.u64 t, %1; cvt.u32.u64 %0, t; }"
        : "=r"(a) : "l"(p));
    return a;
}

__device__ __forceinline__ void cp_async16(uint32_t dst, const void* src) {
    asm volatile("cp.async.cg.shared.global [%0], [%1], 16;"
                 :: "r"(dst), "l"(src) : "memory");
}
__device__ __forceinline__ void cp_commit() {
    asm volatile("cp.async.commit_group;" ::: "memory");
}
template <int N>
__device__ __forceinline__ void cp_wait() {
    asm volatile("cp.async.wait_group %0;" :: "n"(N) : "memory");
}

__device__ __forceinline__ void ldsm_x4(uint32_t& r0, uint32_t& r1,
                                        uint32_t& r2, uint32_t& r3, uint32_t a) {
    asm volatile("ldmatrix.sync.aligned.m8n8.x4.shared.b16 {%0,%1,%2,%3}, [%4];"
                 : "=r"(r0), "=r"(r1), "=r"(r2), "=r"(r3) : "r"(a));
}

__device__ __forceinline__ void mma_bf16(float* d, const uint32_t* a,
                                         const uint32_t* b) {
    asm volatile(
        "mma.sync.aligned.m16n8k16.row.col.f32.bf16.bf16.f32 "
        "{%0,%1,%2,%3}, {%4,%5,%6,%7}, {%8,%9}, {%0,%1,%2,%3};"
        : "+f"(d[0]), "+f"(d[1]), "+f"(d[2]), "+f"(d[3])
        : "r"(a[0]), "r"(a[1]), "r"(a[2]), "r"(a[3]), "r"(b[0]), "r"(b[1]));
}

__device__ __forceinline__ uint32_t bfpack(__nv_bfloat16 a, __nv_bfloat16 b) {
    return ((uint32_t)__bfloat16_as_ushort(b) << 16) | (uint32_t)__bfloat16_as_ushort(a);
}

// Swizzled byte offset within a [128 x 32 bf16] tile (rows of 64B, 4 x 16B chunks).
// chunk_phys = chunk ^ ((row>>1)&3)  -> conflict-free for ldmatrix & cp.async.
__device__ __forceinline__ uint32_t swz(int row, int chunk) {
    return (uint32_t)(row * 64 + ((chunk ^ ((row >> 1) & 3)) << 4));
}

// ---------------------------------------------------------------------------
// Conversion kernels
// ---------------------------------------------------------------------------
// x [M,1024] fp32 -> g_xs [M,2048] bf16 (cols 0..1023 = hi, 1024..2047 = lo)
__global__ __launch_bounds__(256) void split_x_kernel(const float* __restrict__ X,
                                                      __nv_bfloat16* __restrict__ Y) {
    size_t t = (size_t)blockIdx.x * 256 + threadIdx.x;
    size_t e = t * 4;
    int row = (int)(e >> 10);
    int col = (int)(e & 1023);
    float4 v = *(const float4*)(X + e);
    float vv[4] = {v.x, v.y, v.z, v.w};
    __nv_bfloat16 h[4], l[4];
#pragma unroll
    for (int j = 0; j < 4; j++) {
        h[j] = __float2bfloat16(vv[j]);
        l[j] = __float2bfloat16(vv[j] - __bfloat162float(h[j]));
    }
    uint2 ph, pl;
    ph.x = bfpack(h[0], h[1]); ph.y = bfpack(h[2], h[3]);
    pl.x = bfpack(l[0], l[1]); pl.y = bfpack(l[2], l[3]);
    *(uint2*)(Y + (size_t)row * K2 + col)        = ph;
    *(uint2*)(Y + (size_t)row * K2 + 1024 + col) = pl;
}

// W [1024(K),1024(N)] fp32 -> Y [1024(N),2048(K split)] bf16 (transposed)
__global__ __launch_bounds__(256) void wsplit_kernel(const float* __restrict__ W,
                                                     __nv_bfloat16* __restrict__ Y) {
    __shared__ float t[32][33];
    int k0 = blockIdx.x * 32, n0 = blockIdx.y * 32;
    int tx = threadIdx.x, ty = threadIdx.y;   // 32 x 8
#pragma unroll
    for (int i = 0; i < 4; i++)
        t[ty + 8 * i][tx] = W[(size_t)(k0 + ty + 8 * i) * 1024 + n0 + tx];
    __syncthreads();
#pragma unroll
    for (int i = 0; i < 4; i++) {
        int n = n0 + ty + 8 * i;
        float v = t[tx][ty + 8 * i];
        __nv_bfloat16 h = __float2bfloat16(v);
        __nv_bfloat16 l = __float2bfloat16(v - __bfloat162float(h));
        Y[(size_t)n * K2 + k0 + tx]        = h;
        Y[(size_t)n * K2 + 1024 + k0 + tx] = l;
    }
}

// ---------------------------------------------------------------------------
// bf16-split GEMM via mma.sync (legacy HMMA path — arch-agnostic):
//   C[M,N] = A·B^T + bias, near-fp32 accuracy.
// A2: [M,2048] bf16 (hi|lo), B2: [N,2048] bf16 (hi|lo), C fp32.
// CTA: 128x128 tile, 8 warps (2x4), warp tile 64x32, BK=32,
// 96 k-iterations = 3 split passes (hi*hi, lo*hi, hi*lo) x 32 chunks.
// 2-stage cp.async pipeline, XOR-swizzled smem, ldmatrix fragment loads.
// ---------------------------------------------------------------------------
#define NITER 96

__global__ __launch_bounds__(256) void gemm_mma(
    const __nv_bfloat16* __restrict__ A2,
    const __nv_bfloat16* __restrict__ B2,
    const float* __restrict__ bias,
    float* __restrict__ C, int N)
{
    // [stage][A=0/B=1][128 rows x 32 bf16]
    __shared__ __align__(128) __nv_bfloat16 sm[2][2][128 * 32];

    const int tid  = threadIdx.x;
    const int lane = tid & 31;
    const int warp = tid >> 5;
    const int wm   = warp & 1;    // 0..1 : 64-row slab
    const int wn   = warp >> 1;   // 0..3 : 32-col slab
    const int brow = blockIdx.y * 128;
    const int bcol = blockIdx.x * 128;

    const uint32_t sA0 = smem_u32(&sm[0][0][0]);
    const uint32_t sB0 = smem_u32(&sm[0][1][0]);
    const uint32_t stgstride = 2 * 128 * 32 * 2;   // bytes between stages

    float acc[4][4][4];
#pragma unroll
    for (int i = 0; i < 4; i++)
#pragma unroll
        for (int j = 0; j < 4; j++)
#pragma unroll
            for (int e = 0; e < 4; e++) acc[i][j][e] = 0.f;

    // Per-thread global->smem chunk coordinates (2 chunks of A, 2 of B)
    const int r0 = tid >> 2,        c0 = tid & 3;          // chunk idx tid
    const int r1 = (tid + 256) >> 2, c1 = (tid + 256) & 3; // chunk idx tid+256
    const uint32_t so0 = swz(r0, c0), so1 = swz(r1, c1);

    // ldmatrix lane addressing (within a 16x16 fragment group)
    const int lrow  = lane & 15;
    const int lksel = lane >> 4;

#define ISSUE(it, stage)                                                      \
    do {                                                                      \
        int _p  = (it) >> 5;                                                  \
        int _kt = (it) & 31;                                                  \
        int _ao = (_p == 1) ? 1024 : 0;                                       \
        int _bo = (_p == 2) ? 1024 : 0;                                       \
        const __nv_bfloat16* _Ag = A2 + (size_t)brow * K2 + _ao + _kt * 32;   \
        const __nv_bfloat16* _Bg = B2 + (size_t)bcol * K2 + _bo + _kt * 32;   \
        uint32_t _sa = sA0 + (stage) * stgstride;                             \
        uint32_t _sb = sB0 + (stage) * stgstride;                             \
        cp_async16(_sa + so0, _Ag + (size_t)r0 * K2 + c0 * 8);                \
        cp_async16(_sa + so1, _Ag + (size_t)r1 * K2 + c1 * 8);                \
        cp_async16(_sb + so0, _Bg + (size_t)r0 * K2 + c0 * 8);                \
        cp_async16(_sb + so1, _Bg + (size_t)r1 * K2 + c1 * 8);                \
        cp_commit();                                                          \
    } while (0)

    ISSUE(0, 0);

    for (int it = 0; it < NITER; it++) {
        const int cur = it & 1;
        if (it + 1 < NITER) {
            ISSUE(it + 1, cur ^ 1);
            cp_wait<1>();
        } else {
            cp_wait<0>();
        }
        __syncthreads();

        const uint32_t sa = sA0 + cur * stgstride;
        const uint32_t sb = sB0 + cur * stgstride;

#pragma unroll
        for (int ks = 0; ks < 2; ks++) {
            uint32_t a[4][4], b[4][2];
#pragma unroll
            for (int mi = 0; mi < 4; mi++) {
                int row   = wm * 64 + mi * 16 + lrow;
                int chunk = ks * 2 + lksel;
                ldsm_x4(a[mi][0], a[mi][1], a[mi][2], a[mi][3],
                        sa + swz(row, chunk));
            }
#pragma unroll
            for (int nj = 0; nj < 2; nj++) {
                int row   = wn * 32 + nj * 16 + lrow;
                int chunk = ks * 2 + lksel;
                uint32_t t0, t1, t2, t3;
                ldsm_x4(t0, t1, t2, t3, sb + swz(row, chunk));
                b[nj * 2 + 0][0] = t0;  b[nj * 2 + 1][0] = t1;
                b[nj * 2 + 0][1] = t2;  b[nj * 2 + 1][1] = t3;
            }
#pragma unroll
            for (int mi = 0; mi < 4; mi++)
#pragma unroll
                for (int ni = 0; ni < 4; ni++)
                    mma_bf16(acc[mi][ni], a[mi], b[ni]);
        }
        __syncthreads();
    }
#undef ISSUE

    // Epilogue: add bias, fp32 float2 stores.
#pragma unroll
    for (int mi = 0; mi < 4; mi++) {
#pragma unroll
        for (int ni = 0; ni < 4; ni++) {
            int r = brow + wm * 64 + mi * 16 + (lane >> 2);
            int c = bcol + wn * 32 + ni * 8 + (lane & 3) * 2;
            float bx = bias[c], by = bias[c + 1];
            float2 v0 = make_float2(acc[mi][ni][0] + bx, acc[mi][ni][1] + by);
            float2 v1 = make_float2(acc[mi][ni][2] + bx, acc[mi][ni][3] + by);
            *(float2*)(C + (size_t)r * N + c)       = v0;
            *(float2*)(C + (size_t)(r + 8) * N + c) = v1;
        }
    }
}

// ---------------------------------------------------------------------------
// Flash-style attention (fp32 math, vectorized smem access).
// Emits bf16 hi/lo split directly into g_attb for the final tensor-core GEMM.
// ---------------------------------------------------------------------------
__global__ __launch_bounds__(256) void attn_kernel(
    const float* __restrict__ Q, const float* __restrict__ K,
    const float* __restrict__ V, const int* __restrict__ masks)
{
    __shared__ float Qts[DKdim][68];   // [d][q], rows 272B (16B-aligned)
    __shared__ float Kts[DKdim][36];   // [d][k], rows 144B (8B-aligned)
    __shared__ float Vs [32][68];      // [k][d]
    __shared__ float Pts[32][68];      // [k][q]
    __shared__ int   msk[32];

    const int tid = threadIdx.x;
    const int tx  = tid & 15;
    const int ty  = tid >> 4;
    const int b   = blockIdx.z, h = blockIdx.y;
    const int q0  = blockIdx.x * 64;

    const float* Qb = Q + ((size_t)(b * Sdim + q0)) * Ddim + h * DKdim;
    const float* Kb = K + ((size_t)b * Sdim) * Ddim + h * DKdim;
    const float* Vb = V + ((size_t)b * Sdim) * Ddim + h * DKdim;

    // Load Q tile (64 q x 64 d), transposed + pre-scaled by 1/sqrt(DK)
#pragma unroll
    for (int i = 0; i < 4; i++) {
        int idx = tid + i * 256;
        int q   = idx >> 4;
        int dv  = idx & 15;
        float4 v = *(const float4*)(Qb + (size_t)q * Ddim + dv * 4);
        Qts[dv * 4 + 0][q] = v.x * 0.125f;
        Qts[dv * 4 + 1][q] = v.y * 0.125f;
        Qts[dv * 4 + 2][q] = v.z * 0.125f;
        Qts[dv * 4 + 3][q] = v.w * 0.125f;
    }

    float m_i[4], l_i[4], o[4][4];
#pragma unroll
    for (int i = 0; i < 4; i++) {
        m_i[i] = -1e30f; l_i[i] = 0.f;
#pragma unroll
        for (int j = 0; j < 4; j++) o[i][j] = 0.f;
    }

    for (int t = 0; t < Sdim / 32; t++) {
        const int kb = t * 32;
        __syncthreads();

        // Load K (transposed) and V (row-major) tiles
#pragma unroll
        for (int i = 0; i < 2; i++) {
            int idx = tid + i * 256;
            int k   = idx >> 4;
            int dv  = idx & 15;
            float4 kv = *(const float4*)(Kb + (size_t)(kb + k) * Ddim + dv * 4);
            Kts[dv * 4 + 0][k] = kv.x;
            Kts[dv * 4 + 1][k] = kv.y;
            Kts[dv * 4 + 2][k] = kv.z;
            Kts[dv * 4 + 3][k] = kv.w;
            *(float4*)&Vs[k][dv * 4] =
                *(const float4*)(Vb + (size_t)(kb + k) * Ddim + dv * 4);
        }
        if (tid < 32) msk[tid] = masks[b * Sdim + kb + tid];
        __syncthreads();

        // Scores: s[4 queries][2 keys] — vectorized smem reads
        float s[4][2] = {{0.f, 0.f}, {0.f, 0.f}, {0.f, 0.f}, {0.f, 0.f}};
#pragma unroll 8
        for (int d = 0; d < DKdim; d++) {
            float4 a  = *(const float4*)&Qts[d][ty * 4];
            float2 bk = *(const float2*)&Kts[d][tx * 2];
            s[0][0] += a.x * bk.x;  s[0][1] += a.x * bk.y;
            s[1][0] += a.y * bk.x;  s[1][1] += a.y * bk.y;
            s[2][0] += a.z * bk.x;  s[2][1] += a.z * bk.y;
            s[3][0] += a.w * bk.x;  s[3][1] += a.w * bk.y;
        }
#pragma unroll
        for (int j = 0; j < 2; j++) {
            if (msk[tx * 2 + j] == 0) {
#pragma unroll
                for (int i = 0; i < 4; i++) s[i][j] = -1e9f;
            }
        }

        // Online softmax update (16 tx lanes share each query row)
#pragma unroll
        for (int i = 0; i < 4; i++) {
            float tmax = fmaxf(s[i][0], s[i][1]);
#pragma unroll
            for (int off = 8; off; off >>= 1)
                tmax = fmaxf(tmax, __shfl_xor_sync(0xffffffffu, tmax, off));
            float nm   = fmaxf(m_i[i], tmax);
            float corr = __expf(m_i[i] - nm);
            float p0   = __expf(s[i][0] - nm);
            float p1   = __expf(s[i][1] - nm);
            float ts   = p0 + p1;
#pragma unroll
            for (int off = 8; off; off >>= 1)
                ts += __shfl_xor_sync(0xffffffffu, ts, off);
            l_i[i] = l_i[i] * corr + ts;
            m_i[i] = nm;
#pragma unroll
            for (int j = 0; j < 4; j++) o[i][j] *= corr;
            Pts[tx * 2 + 0][ty * 4 + i] = p0;
            Pts[tx * 2 + 1][ty * 4 + i] = p1;
        }
        __syncthreads();

        // O += P * V — vectorized smem reads
#pragma unroll 8
        for (int k = 0; k < 32; k++) {
            float4 a  = *(const float4*)&Pts[k][ty * 4];
            float4 bv = *(const float4*)&Vs[k][tx * 4];
            o[0][0] += a.x * bv.x;  o[0][1] += a.x * bv.y;  o[0][2] += a.x * bv.z;  o[0][3] += a.x * bv.w;
            o[1][0] += a.y * bv.x;  o[1][1] += a.y * bv.y;  o[1][2] += a.y * bv.z;  o[1][3] += a.y * bv.w;
            o[2][0] += a.z * bv.x;  o[2][1] += a.z * bv.y;  o[2][2] += a.z * bv.z;  o[2][3] += a.z * bv.w;
            o[3][0] += a.w * bv.x;  o[3][1] += a.w * bv.y;  o[3][2] += a.w * bv.z;  o[3][3] += a.w * bv.w;
        }
    }

    // Normalize + write bf16 hi/lo split into g_attb [M, 2048]
#pragma unroll
    for (int i = 0; i < 4; i++) {
        float inv = 1.0f / l_i[i];
        float vv[4];
#pragma unroll
        for (int j = 0; j < 4; j++) vv[j] = o[i][j] * inv;
        int row = b * Sdim + q0 + ty * 4 + i;
        int col = h * DKdim + tx * 4;
        __nv_bfloat16 hb[4], lb[4];
#pragma unroll
        for (int j = 0; j < 4; j++) {
            hb[j] = __float2bfloat16(vv[j]);
            lb[j] = __float2bfloat16(vv[j] - __bfloat162float(hb[j]));
        }
        uint2 ph, pl;
        ph.x = bfpack(hb[0], hb[1]); ph.y = bfpack(hb[2], hb[3]);
        pl.x = bfpack(lb[0], lb[1]); pl.y = bfpack(lb[2], lb[3]);
        *(uint2*)(&g_attb[(size_t)row * K2 + col])        = ph;
        *(uint2*)(&g_attb[(size_t)row * K2 + 1024 + col]) = pl;
    }
}

// ---------------------------------------------------------------------------
// kernel_launch: graph-capturable, allocation-free.
// Input order: x, masks, Wq, bq, Wk, bk, Wv, bv, Wo, bo
// ---------------------------------------------------------------------------
extern "C" void kernel_launch(void* const* d_in, const int* in_sizes, int n_in,
                              void* d_out, int out_size)
{
    const float* x     = (const float*)d_in[0];
    const int*   masks = (const int*)  d_in[1];
    const float* Wq    = (const float*)d_in[2];
    const float* bq    = (const float*)d_in[3];
    const float* Wk    = (const float*)d_in[4];
    const float* bk    = (const float*)d_in[5];
    const float* Wv    = (const float*)d_in[6];
    const float* bv    = (const float*)d_in[7];
    const float* Wo    = (const float*)d_in[8];
    const float* bo    = (const float*)d_in[9];
    float* out = (float*)d_out;

    __nv_bfloat16 *xs, *wq2, *wk2, *wv2, *wo2, *attb;
    float *q, *k, *v;
    cudaGetSymbolAddress((void**)&xs,   g_xs);
    cudaGetSymbolAddress((void**)&wq2,  g_wq);
    cudaGetSymbolAddress((void**)&wk2,  g_wk);
    cudaGetSymbolAddress((void**)&wv2,  g_wv);
    cudaGetSymbolAddress((void**)&wo2,  g_wo);
    cudaGetSymbolAddress((void**)&q,    g_q);
    cudaGetSymbolAddress((void**)&k,    g_k);
    cudaGetSymbolAddress((void**)&v,    g_v);
    cudaGetSymbolAddress((void**)&attb, g_attb);

    // fp32 -> bf16 hi/lo conversions
    split_x_kernel<<<(Mdim * Ddim) / 4 / 256, 256>>>(x, xs);
    dim3 wgrid(32, 32), wblk(32, 8);
    wsplit_kernel<<<wgrid, wblk>>>(Wq, wq2);
    wsplit_kernel<<<wgrid, wblk>>>(Wk, wk2);
    wsplit_kernel<<<wgrid, wblk>>>(Wv, wv2);
    wsplit_kernel<<<wgrid, wblk>>>(Wo, wo2);

    // Projections via mma.sync bf16-split GEMM
    dim3 gg(Ddim / 128, Mdim / 128);   // (8, 64)
    gemm_mma<<<gg, 256>>>(xs, wq2, bq, q, Ddim);
    gemm_mma<<<gg, 256>>>(xs, wk2, bk, k, Ddim);
    gemm_mma<<<gg, 256>>>(xs, wv2, bv, v, Ddim);

    // Attention (fp32) -> bf16 split output
    dim3 ga(Sdim / 64, Hdim, Bdim);    // (16, 16, 8)
    attn_kernel<<<ga, 256>>>(q, k, v, masks);

    // Output projection
    gemm_mma<<<gg, 256>>>(attb, wo2, bo, out, Ddim);
}

// round 10
// speedup vs baseline: 1.5517x; 1.0005x over previous
#include <cuda_runtime.h>
#include <cuda_bf16.h>
#include <cstdint>

// Problem dims (fixed by the reference)
#define Bdim  8
#define Sdim  1024
#define Ddim  1024
#define Hdim  16
#define DKdim 64
#define Mdim  (Bdim * Sdim)   // 8192 rows
#define K2    2048            // split-K width (hi | lo)

// ---------------------------------------------------------------------------
// Scratch (__device__ globals; no cudaMalloc allowed)
// ---------------------------------------------------------------------------
__device__ __nv_bfloat16 g_xs  [(size_t)Mdim * K2];   // x  split   [M,2048]
__device__ __nv_bfloat16 g_wq  [(size_t)Ddim * K2];   // Wq^T split [N,2048]
__device__ __nv_bfloat16 g_wk  [(size_t)Ddim * K2];
__device__ __nv_bfloat16 g_wv  [(size_t)Ddim * K2];
__device__ __nv_bfloat16 g_wo  [(size_t)Ddim * K2];
__device__ float         g_q   [(size_t)Mdim * Ddim];
__device__ float         g_k   [(size_t)Mdim * Ddim];
__device__ float         g_v   [(size_t)Mdim * Ddim];
__device__ __nv_bfloat16 g_attb[(size_t)Mdim * K2];   // attn out split [M,2048]

// ---------------------------------------------------------------------------
// Helpers (arch-agnostic PTX only: cp.async, ldmatrix, mma.sync)
// ---------------------------------------------------------------------------
__device__ __forceinline__ uint32_t smem_u32(const void* p) {
    uint32_t a;
    asm("{ .reg .u64 t; cvta.to.shared.u64 t, %1; cvt.u32.u64 %0, t; }"
        : "=r"(a) : "l"(p));
    return a;
}

__device__ __forceinline__ void cp_async16(uint32_t dst, const void* src) {
    asm volatile("cp.async.cg.shared.global [%0], [%1], 16;"
                 :: "r"(dst), "l"(src) : "memory");
}
__device__ __forceinline__ void cp_commit() {
    asm volatile("cp.async.commit_group;" ::: "memory");
}
template <int N>
__device__ __forceinline__ void cp_wait() {
    asm volatile("cp.async.wait_group %0;" :: "n"(N) : "memory");
}

__device__ __forceinline__ void ldsm_x4(uint32_t& r0, uint32_t& r1,
                                        uint32_t& r2, uint32_t& r3, uint32_t a) {
    asm volatile("ldmatrix.sync.aligned.m8n8.x4.shared.b16 {%0,%1,%2,%3}, [%4];"
                 : "=r"(r0), "=r"(r1), "=r"(r2), "=r"(r3) : "r"(a));
}

__device__ __forceinline__ void mma_bf16(float* d, const uint32_t* a,
                                         const uint32_t* b) {
    asm volatile(
        "mma.sync.aligned.m16n8k16.row.col.f32.bf16.bf16.f32 "
        "{%0,%1,%2,%3}, {%4,%5,%6,%7}, {%8,%9}, {%0,%1,%2,%3};"
        : "+f"(d[0]), "+f"(d[1]), "+f"(d[2]), "+f"(d[3])
        : "r"(a[0]), "r"(a[1]), "r"(a[2]), "r"(a[3]), "r"(b[0]), "r"(b[1]));
}

__device__ __forceinline__ uint32_t bfpack(__nv_bfloat16 a, __nv_bfloat16 b) {
    return ((uint32_t)__bfloat16_as_ushort(b) << 16) | (uint32_t)__bfloat16_as_ushort(a);
}

// Swizzled byte offset within a [128 x 32 bf16] tile (rows of 64B, 4 x 16B chunks).
// chunk_phys = chunk ^ ((row>>1)&3)  -> conflict-free for ldmatrix & cp.async.
__device__ __forceinline__ uint32_t swz(int row, int chunk) {
    return (uint32_t)(row * 64 + ((chunk ^ ((row >> 1) & 3)) << 4));
}

// ---------------------------------------------------------------------------
// Conversion kernels
// ---------------------------------------------------------------------------
// x [M,1024] fp32 -> g_xs [M,2048] bf16 (cols 0..1023 = hi, 1024..2047 = lo)
__global__ __launch_bounds__(256) void split_x_kernel(const float* __restrict__ X,
                                                      __nv_bfloat16* __restrict__ Y) {
    size_t t = (size_t)blockIdx.x * 256 + threadIdx.x;
    size_t e = t * 4;
    int row = (int)(e >> 10);
    int col = (int)(e & 1023);
    float4 v = *(const float4*)(X + e);
    float vv[4] = {v.x, v.y, v.z, v.w};
    __nv_bfloat16 h[4], l[4];
#pragma unroll
    for (int j = 0; j < 4; j++) {
        h[j] = __float2bfloat16(vv[j]);
        l[j] = __float2bfloat16(vv[j] - __bfloat162float(h[j]));
    }
    uint2 ph, pl;
    ph.x = bfpack(h[0], h[1]); ph.y = bfpack(h[2], h[3]);
    pl.x = bfpack(l[0], l[1]); pl.y = bfpack(l[2], l[3]);
    *(uint2*)(Y + (size_t)row * K2 + col)        = ph;
    *(uint2*)(Y + (size_t)row * K2 + 1024 + col) = pl;
}

// W [1024(K),1024(N)] fp32 -> Y [1024(N),2048(K split)] bf16 (transposed)
__global__ __launch_bounds__(256) void wsplit_kernel(const float* __restrict__ W,
                                                     __nv_bfloat16* __restrict__ Y) {
    __shared__ float t[32][33];
    int k0 = blockIdx.x * 32, n0 = blockIdx.y * 32;
    int tx = threadIdx.x, ty = threadIdx.y;   // 32 x 8
#pragma unroll
    for (int i = 0; i < 4; i++)
        t[ty + 8 * i][tx] = W[(size_t)(k0 + ty + 8 * i) * 1024 + n0 + tx];
    __syncthreads();
#pragma unroll
    for (int i = 0; i < 4; i++) {
        int n = n0 + ty + 8 * i;
        float v = t[tx][ty + 8 * i];
        __nv_bfloat16 h = __float2bfloat16(v);
        __nv_bfloat16 l = __float2bfloat16(v - __bfloat162float(h));
        Y[(size_t)n * K2 + k0 + tx]        = h;
        Y[(size_t)n * K2 + 1024 + k0 + tx] = l;
    }
}

// ---------------------------------------------------------------------------
// bf16-split GEMM via mma.sync (legacy HMMA path — arch-agnostic):
//   C[M,N] = A·B^T + bias, near-fp32 accuracy.
// A2: [M,2048] bf16 (hi|lo), B2: [N,2048] bf16 (hi|lo), C fp32.
// CTA: 128x128 tile, 8 warps (2x4), warp tile 64x32, BK=32,
// 96 k-iterations = 3 split passes (hi*hi, lo*hi, hi*lo) x 32 chunks.
// 2-stage cp.async pipeline, XOR-swizzled smem, ldmatrix fragment loads.
// ---------------------------------------------------------------------------
#define NITER 96

__global__ __launch_bounds__(256) void gemm_mma(
    const __nv_bfloat16* __restrict__ A2,
    const __nv_bfloat16* __restrict__ B2,
    const float* __restrict__ bias,
    float* __restrict__ C, int N)
{
    // [stage][A=0/B=1][128 rows x 32 bf16]
    __shared__ __align__(128) __nv_bfloat16 sm[2][2][128 * 32];

    const int tid  = threadIdx.x;
    const int lane = tid & 31;
    const int warp = tid >> 5;
    const int wm   = warp & 1;    // 0..1 : 64-row slab
    const int wn   = warp >> 1;   // 0..3 : 32-col slab
    const int brow = blockIdx.y * 128;
    const int bcol = blockIdx.x * 128;

    const uint32_t sA0 = smem_u32(&sm[0][0][0]);
    const uint32_t sB0 = smem_u32(&sm[0][1][0]);
    const uint32_t stgstride = 2 * 128 * 32 * 2;   // bytes between stages

    float acc[4][4][4];
#pragma unroll
    for (int i = 0; i < 4; i++)
#pragma unroll
        for (int j = 0; j < 4; j++)
#pragma unroll
            for (int e = 0; e < 4; e++) acc[i][j][e] = 0.f;

    // Per-thread global->smem chunk coordinates (2 chunks of A, 2 of B)
    const int r0 = tid >> 2,        c0 = tid & 3;          // chunk idx tid
    const int r1 = (tid + 256) >> 2, c1 = (tid + 256) & 3; // chunk idx tid+256
    const uint32_t so0 = swz(r0, c0), so1 = swz(r1, c1);

    // ldmatrix lane addressing (within a 16x16 fragment group)
    const int lrow  = lane & 15;
    const int lksel = lane >> 4;

#define ISSUE(it, stage)                                                      \
    do {                                                                      \
        int _p  = (it) >> 5;                                                  \
        int _kt = (it) & 31;                                                  \
        int _ao = (_p == 1) ? 1024 : 0;                                       \
        int _bo = (_p == 2) ? 1024 : 0;                                       \
        const __nv_bfloat16* _Ag = A2 + (size_t)brow * K2 + _ao + _kt * 32;   \
        const __nv_bfloat16* _Bg = B2 + (size_t)bcol * K2 + _bo + _kt * 32;   \
        uint32_t _sa = sA0 + (stage) * stgstride;                             \
        uint32_t _sb = sB0 + (stage) * stgstride;                             \
        cp_async16(_sa + so0, _Ag + (size_t)r0 * K2 + c0 * 8);                \
        cp_async16(_sa + so1, _Ag + (size_t)r1 * K2 + c1 * 8);                \
        cp_async16(_sb + so0, _Bg + (size_t)r0 * K2 + c0 * 8);                \
        cp_async16(_sb + so1, _Bg + (size_t)r1 * K2 + c1 * 8);                \
        cp_commit();                                                          \
    } while (0)

    ISSUE(0, 0);

    for (int it = 0; it < NITER; it++) {
        const int cur = it & 1;
        if (it + 1 < NITER) {
            ISSUE(it + 1, cur ^ 1);
            cp_wait<1>();
        } else {
            cp_wait<0>();
        }
        __syncthreads();

        const uint32_t sa = sA0 + cur * stgstride;
        const uint32_t sb = sB0 + cur * stgstride;

#pragma unroll
        for (int ks = 0; ks < 2; ks++) {
            uint32_t a[4][4], b[4][2];
#pragma unroll
            for (int mi = 0; mi < 4; mi++) {
                int row   = wm * 64 + mi * 16 + lrow;
                int chunk = ks * 2 + lksel;
                ldsm_x4(a[mi][0], a[mi][1], a[mi][2], a[mi][3],
                        sa + swz(row, chunk));
            }
#pragma unroll
            for (int nj = 0; nj < 2; nj++) {
                int row   = wn * 32 + nj * 16 + lrow;
                int chunk = ks * 2 + lksel;
                uint32_t t0, t1, t2, t3;
                ldsm_x4(t0, t1, t2, t3, sb + swz(row, chunk));
                b[nj * 2 + 0][0] = t0;  b[nj * 2 + 1][0] = t1;
                b[nj * 2 + 0][1] = t2;  b[nj * 2 + 1][1] = t3;
            }
#pragma unroll
            for (int mi = 0; mi < 4; mi++)
#pragma unroll
                for (int ni = 0; ni < 4; ni++)
                    mma_bf16(acc[mi][ni], a[mi], b[ni]);
        }
        __syncthreads();
    }
#undef ISSUE

    // Epilogue: add bias, fp32 float2 stores.
#pragma unroll
    for (int mi = 0; mi < 4; mi++) {
#pragma unroll
        for (int ni = 0; ni < 4; ni++) {
            int r = brow + wm * 64 + mi * 16 + (lane >> 2);
            int c = bcol + wn * 32 + ni * 8 + (lane & 3) * 2;
            float bx = bias[c], by = bias[c + 1];
            float2 v0 = make_float2(acc[mi][ni][0] + bx, acc[mi][ni][1] + by);
            float2 v1 = make_float2(acc[mi][ni][2] + bx, acc[mi][ni][3] + by);
            *(float2*)(C + (size_t)r * N + c)       = v0;
            *(float2*)(C + (size_t)(r + 8) * N + c) = v1;
        }
    }
}

// ---------------------------------------------------------------------------
// Flash-style attention (fp32 math, vectorized smem access).
// Emits bf16 hi/lo split directly into g_attb for the final tensor-core GEMM.
// ---------------------------------------------------------------------------
__global__ __launch_bounds__(256) void attn_kernel(
    const float* __restrict__ Q, const float* __restrict__ K,
    const float* __restrict__ V, const int* __restrict__ masks)
{
    __shared__ float Qts[DKdim][68];   // [d][q], rows 272B (16B-aligned)
    __shared__ float Kts[DKdim][36];   // [d][k], rows 144B (8B-aligned)
    __shared__ float Vs [32][68];      // [k][d]
    __shared__ float Pts[32][68];      // [k][q]
    __shared__ int   msk[32];

    const int tid = threadIdx.x;
    const int tx  = tid & 15;
    const int ty  = tid >> 4;
    const int b   = blockIdx.z, h = blockIdx.y;
    const int q0  = blockIdx.x * 64;

    const float* Qb = Q + ((size_t)(b * Sdim + q0)) * Ddim + h * DKdim;
    const float* Kb = K + ((size_t)b * Sdim) * Ddim + h * DKdim;
    const float* Vb = V + ((size_t)b * Sdim) * Ddim + h * DKdim;

    // Load Q tile (64 q x 64 d), transposed + pre-scaled by 1/sqrt(DK)
#pragma unroll
    for (int i = 0; i < 4; i++) {
        int idx = tid + i * 256;
        int q   = idx >> 4;
        int dv  = idx & 15;
        float4 v = *(const float4*)(Qb + (size_t)q * Ddim + dv * 4);
        Qts[dv * 4 + 0][q] = v.x * 0.125f;
        Qts[dv * 4 + 1][q] = v.y * 0.125f;
        Qts[dv * 4 + 2][q] = v.z * 0.125f;
        Qts[dv * 4 + 3][q] = v.w * 0.125f;
    }

    float m_i[4], l_i[4], o[4][4];
#pragma unroll
    for (int i = 0; i < 4; i++) {
        m_i[i] = -1e30f; l_i[i] = 0.f;
#pragma unroll
        for (int j = 0; j < 4; j++) o[i][j] = 0.f;
    }

    for (int t = 0; t < Sdim / 32; t++) {
        const int kb = t * 32;
        __syncthreads();

        // Load K (transposed) and V (row-major) tiles
#pragma unroll
        for (int i = 0; i < 2; i++) {
            int idx = tid + i * 256;
            int k   = idx >> 4;
            int dv  = idx & 15;
            float4 kv = *(const float4*)(Kb + (size_t)(kb + k) * Ddim + dv * 4);
            Kts[dv * 4 + 0][k] = kv.x;
            Kts[dv * 4 + 1][k] = kv.y;
            Kts[dv * 4 + 2][k] = kv.z;
            Kts[dv * 4 + 3][k] = kv.w;
            *(float4*)&Vs[k][dv * 4] =
                *(const float4*)(Vb + (size_t)(kb + k) * Ddim + dv * 4);
        }
        if (tid < 32) msk[tid] = masks[b * Sdim + kb + tid];
        __syncthreads();

        // Scores: s[4 queries][2 keys] — vectorized smem reads
        float s[4][2] = {{0.f, 0.f}, {0.f, 0.f}, {0.f, 0.f}, {0.f, 0.f}};
#pragma unroll 8
        for (int d = 0; d < DKdim; d++) {
            float4 a  = *(const float4*)&Qts[d][ty * 4];
            float2 bk = *(const float2*)&Kts[d][tx * 2];
            s[0][0] += a.x * bk.x;  s[0][1] += a.x * bk.y;
            s[1][0] += a.y * bk.x;  s[1][1] += a.y * bk.y;
            s[2][0] += a.z * bk.x;  s[2][1] += a.z * bk.y;
            s[3][0] += a.w * bk.x;  s[3][1] += a.w * bk.y;
        }
#pragma unroll
        for (int j = 0; j < 2; j++) {
            if (msk[tx * 2 + j] == 0) {
#pragma unroll
                for (int i = 0; i < 4; i++) s[i][j] = -1e9f;
            }
        }

        // Online softmax update (16 tx lanes share each query row)
#pragma unroll
        for (int i = 0; i < 4; i++) {
            float tmax = fmaxf(s[i][0], s[i][1]);
#pragma unroll
            for (int off = 8; off; off >>= 1)
                tmax = fmaxf(tmax, __shfl_xor_sync(0xffffffffu, tmax, off));
            float nm   = fmaxf(m_i[i], tmax);
            float corr = __expf(m_i[i] - nm);
            float p0   = __expf(s[i][0] - nm);
            float p1   = __expf(s[i][1] - nm);
            float ts   = p0 + p1;
#pragma unroll
            for (int off = 8; off; off >>= 1)
                ts += __shfl_xor_sync(0xffffffffu, ts, off);
            l_i[i] = l_i[i] * corr + ts;
            m_i[i] = nm;
#pragma unroll
            for (int j = 0; j < 4; j++) o[i][j] *= corr;
            Pts[tx * 2 + 0][ty * 4 + i] = p0;
            Pts[tx * 2 + 1][ty * 4 + i] = p1;
        }
        __syncthreads();

        // O += P * V — vectorized smem reads
#pragma unroll 8
        for (int k = 0; k < 32; k++) {
            float4 a  = *(const float4*)&Pts[k][ty * 4];
            float4 bv = *(const float4*)&Vs[k][tx * 4];
            o[0][0] += a.x * bv.x;  o[0][1] += a.x * bv.y;  o[0][2] += a.x * bv.z;  o[0][3] += a.x * bv.w;
            o[1][0] += a.y * bv.x;  o[1][1] += a.y * bv.y;  o[1][2] += a.y * bv.z;  o[1][3] += a.y * bv.w;
            o[2][0] += a.z * bv.x;  o[2][1] += a.z * bv.y;  o[2][2] += a.z * bv.z;  o[2][3] += a.z * bv.w;
            o[3][0] += a.w * bv.x;  o[3][1] += a.w * bv.y;  o[3][2] += a.w * bv.z;  o[3][3] += a.w * bv.w;
        }
    }

    // Normalize + write bf16 hi/lo split into g_attb [M, 2048]
#pragma unroll
    for (int i = 0; i < 4; i++) {
        float inv = 1.0f / l_i[i];
        float vv[4];
#pragma unroll
        for (int j = 0; j < 4; j++) vv[j] = o[i][j] * inv;
        int row = b * Sdim + q0 + ty * 4 + i;
        int col = h * DKdim + tx * 4;
        __nv_bfloat16 hb[4], lb[4];
#pragma unroll
        for (int j = 0; j < 4; j++) {
            hb[j] = __float2bfloat16(vv[j]);
            lb[j] = __float2bfloat16(vv[j] - __bfloat162float(hb[j]));
        }
        uint2 ph, pl;
        ph.x = bfpack(hb[0], hb[1]); ph.y = bfpack(hb[2], hb[3]);
        pl.x = bfpack(lb[0], lb[1]); pl.y = bfpack(lb[2], lb[3]);
        *(uint2*)(&g_attb[(size_t)row * K2 + col])        = ph;
        *(uint2*)(&g_attb[(size_t)row * K2 + 1024 + col]) = pl;
    }
}

// ---------------------------------------------------------------------------
// kernel_launch: graph-capturable, allocation-free.
// Input order: x, masks, Wq, bq, Wk, bk, Wv, bv, Wo, bo
// ---------------------------------------------------------------------------
extern "C" void kernel_launch(void* const* d_in, const int* in_sizes, int n_in,
                              void* d_out, int out_size)
{
    const float* x     = (const float*)d_in[0];
    const int*   masks = (const int*)  d_in[1];
    const float* Wq    = (const float*)d_in[2];
    const float* bq    = (const float*)d_in[3];
    const float* Wk    = (const float*)d_in[4];
    const float* bk    = (const float*)d_in[5];
    const float* Wv    = (const float*)d_in[6];
    const float* bv    = (const float*)d_in[7];
    const float* Wo    = (const float*)d_in[8];
    const float* bo    = (const float*)d_in[9];
    float* out = (float*)d_out;

    __nv_bfloat16 *xs, *wq2, *wk2, *wv2, *wo2, *attb;
    float *q, *k, *v;
    cudaGetSymbolAddress((void**)&xs,   g_xs);
    cudaGetSymbolAddress((void**)&wq2,  g_wq);
    cudaGetSymbolAddress((void**)&wk2,  g_wk);
    cudaGetSymbolAddress((void**)&wv2,  g_wv);
    cudaGetSymbolAddress((void**)&wo2,  g_wo);
    cudaGetSymbolAddress((void**)&q,    g_q);
    cudaGetSymbolAddress((void**)&k,    g_k);
    cudaGetSymbolAddress((void**)&v,    g_v);
    cudaGetSymbolAddress((void**)&attb, g_attb);

    // fp32 -> bf16 hi/lo conversions
    split_x_kernel<<<(Mdim * Ddim) / 4 / 256, 256>>>(x, xs);
    dim3 wgrid(32, 32), wblk(32, 8);
    wsplit_kernel<<<wgrid, wblk>>>(Wq, wq2);
    wsplit_kernel<<<wgrid, wblk>>>(Wk, wk2);
    wsplit_kernel<<<wgrid, wblk>>>(Wv, wv2);
    wsplit_kernel<<<wgrid, wblk>>>(Wo, wo2);

    // Projections via mma.sync bf16-split GEMM
    dim3 gg(Ddim / 128, Mdim / 128);   // (8, 64)
    gemm_mma<<<gg, 256>>>(xs, wq2, bq, q, Ddim);
    gemm_mma<<<gg, 256>>>(xs, wk2, bk, k, Ddim);
    gemm_mma<<<gg, 256>>>(xs, wv2, bv, v, Ddim);

    // Attention (fp32) -> bf16 split output
    dim3 ga(Sdim / 64, Hdim, Bdim);    // (16, 16, 8)
    attn_kernel<<<ga, 256>>>(q, k, v, masks);

    // Output projection
    gemm_mma<<<gg, 256>>>(attb, wo2, bo, out, Ddim);
}

// round 11
// speedup vs baseline: 1.5522x; 1.0003x over previous
#include <cuda_runtime.h>
#include <cuda_bf16.h>
#include <cstdint>

// Problem dims (fixed by the reference)
#define Bdim  8
#define Sdim  1024
#define Ddim  1024
#define Hdim  16
#define DKdim 64
#define Mdim  (Bdim * Sdim)   // 8192 rows
#define K2    2048            // split-K width (hi | lo)

// ---------------------------------------------------------------------------
// Scratch (__device__ globals; no cudaMalloc allowed)
// ---------------------------------------------------------------------------
__device__ __nv_bfloat16 g_xs  [(size_t)Mdim * K2];   // x  split   [M,2048]
__device__ __nv_bfloat16 g_wq  [(size_t)Ddim * K2];   // Wq^T split [N,2048]
__device__ __nv_bfloat16 g_wk  [(size_t)Ddim * K2];
__device__ __nv_bfloat16 g_wv  [(size_t)Ddim * K2];
__device__ __nv_bfloat16 g_wo  [(size_t)Ddim * K2];
__device__ float         g_q   [(size_t)Mdim * Ddim];
__device__ float         g_k   [(size_t)Mdim * Ddim];
__device__ float         g_v   [(size_t)Mdim * Ddim];
__device__ __nv_bfloat16 g_attb[(size_t)Mdim * K2];   // attn out split [M,2048]

// ---------------------------------------------------------------------------
// Helpers (arch-agnostic PTX only: cp.async, ldmatrix, mma.sync)
// ---------------------------------------------------------------------------
__device__ __forceinline__ uint32_t smem_u32(const void* p) {
    uint32_t a;
    asm("{ .reg .u64 t; cvta.to.shared.u64 t, %1; cvt.u32.u64 %0, t; }"
        : "=r"(a) : "l"(p));
    return a;
}

__device__ __forceinline__ void cp_async16(uint32_t dst, const void* src) {
    asm volatile("cp.async.cg.shared.global [%0], [%1], 16;"
                 :: "r"(dst), "l"(src) : "memory");
}
__device__ __forceinline__ void cp_commit() {
    asm volatile("cp.async.commit_group;" ::: "memory");
}
template <int N>
__device__ __forceinline__ void cp_wait() {
    asm volatile("cp.async.wait_group %0;" :: "n"(N) : "memory");
}

__device__ __forceinline__ void ldsm_x4(uint32_t& r0, uint32_t& r1,
                                        uint32_t& r2, uint32_t& r3, uint32_t a) {
    asm volatile("ldmatrix.sync.aligned.m8n8.x4.shared.b16 {%0,%1,%2,%3}, [%4];"
                 : "=r"(r0), "=r"(r1), "=r"(r2), "=r"(r3) : "r"(a));
}

__device__ __forceinline__ void mma_bf16(float* d, const uint32_t* a,
                                         const uint32_t* b) {
    asm volatile(
        "mma.sync.aligned.m16n8k16.row.col.f32.bf16.bf16.f32 "
        "{%0,%1,%2,%3}, {%4,%5,%6,%7}, {%8,%9}, {%0,%1,%2,%3};"
        : "+f"(d[0]), "+f"(d[1]), "+f"(d[2]), "+f"(d[3])
        : "r"(a[0]), "r"(a[1]), "r"(a[2]), "r"(a[3]), "r"(b[0]), "r"(b[1]));
}

__device__ __forceinline__ uint32_t bfpack(__nv_bfloat16 a, __nv_bfloat16 b) {
    return ((uint32_t)__bfloat16_as_ushort(b) << 16) | (uint32_t)__bfloat16_as_ushort(a);
}

// Swizzled byte offset within a [128 x 32 bf16] tile (rows of 64B, 4 x 16B chunks).
// chunk_phys = chunk ^ ((row>>1)&3)  -> conflict-free for ldmatrix & cp.async.
__device__ __forceinline__ uint32_t swz(int row, int chunk) {
    return (uint32_t)(row * 64 + ((chunk ^ ((row >> 1) & 3)) << 4));
}

// ---------------------------------------------------------------------------
// Conversion kernels
// ---------------------------------------------------------------------------
// x [M,1024] fp32 -> g_xs [M,2048] bf16 (cols 0..1023 = hi, 1024..2047 = lo)
__global__ __launch_bounds__(256) void split_x_kernel(const float* __restrict__ X,
                                                      __nv_bfloat16* __restrict__ Y) {
    size_t t = (size_t)blockIdx.x * 256 + threadIdx.x;
    size_t e = t * 4;
    int row = (int)(e >> 10);
    int col = (int)(e & 1023);
    float4 v = *(const float4*)(X + e);
    float vv[4] = {v.x, v.y, v.z, v.w};
    __nv_bfloat16 h[4], l[4];
#pragma unroll
    for (int j = 0; j < 4; j++) {
        h[j] = __float2bfloat16(vv[j]);
        l[j] = __float2bfloat16(vv[j] - __bfloat162float(h[j]));
    }
    uint2 ph, pl;
    ph.x = bfpack(h[0], h[1]); ph.y = bfpack(h[2], h[3]);
    pl.x = bfpack(l[0], l[1]); pl.y = bfpack(l[2], l[3]);
    *(uint2*)(Y + (size_t)row * K2 + col)        = ph;
    *(uint2*)(Y + (size_t)row * K2 + 1024 + col) = pl;
}

// W [1024(K),1024(N)] fp32 -> Y [1024(N),2048(K split)] bf16 (transposed)
__global__ __launch_bounds__(256) void wsplit_kernel(const float* __restrict__ W,
                                                     __nv_bfloat16* __restrict__ Y) {
    __shared__ float t[32][33];
    int k0 = blockIdx.x * 32, n0 = blockIdx.y * 32;
    int tx = threadIdx.x, ty = threadIdx.y;   // 32 x 8
#pragma unroll
    for (int i = 0; i < 4; i++)
        t[ty + 8 * i][tx] = W[(size_t)(k0 + ty + 8 * i) * 1024 + n0 + tx];
    __syncthreads();
#pragma unroll
    for (int i = 0; i < 4; i++) {
        int n = n0 + ty + 8 * i;
        float v = t[tx][ty + 8 * i];
        __nv_bfloat16 h = __float2bfloat16(v);
        __nv_bfloat16 l = __float2bfloat16(v - __bfloat162float(h));
        Y[(size_t)n * K2 + k0 + tx]        = h;
        Y[(size_t)n * K2 + 1024 + k0 + tx] = l;
    }
}

// ---------------------------------------------------------------------------
// bf16-split GEMM via mma.sync (legacy HMMA path — arch-agnostic):
//   C[M,N] = A·B^T + bias, near-fp32 accuracy.
// A2: [M,2048] bf16 (hi|lo), B2: [N,2048] bf16 (hi|lo), C fp32.
// CTA: 128x128 tile, 8 warps (2x4), warp tile 64x32, BK=32,
// 96 k-iterations = 3 split passes (hi*hi, lo*hi, hi*lo) x 32 chunks.
// 2-stage cp.async pipeline, XOR-swizzled smem, ldmatrix fragment loads.
// ---------------------------------------------------------------------------
#define NITER 96

__global__ __launch_bounds__(256) void gemm_mma(
    const __nv_bfloat16* __restrict__ A2,
    const __nv_bfloat16* __restrict__ B2,
    const float* __restrict__ bias,
    float* __restrict__ C, int N)
{
    // [stage][A=0/B=1][128 rows x 32 bf16]
    __shared__ __align__(128) __nv_bfloat16 sm[2][2][128 * 32];

    const int tid  = threadIdx.x;
    const int lane = tid & 31;
    const int warp = tid >> 5;
    const int wm   = warp & 1;    // 0..1 : 64-row slab
    const int wn   = warp >> 1;   // 0..3 : 32-col slab
    const int brow = blockIdx.y * 128;
    const int bcol = blockIdx.x * 128;

    const uint32_t sA0 = smem_u32(&sm[0][0][0]);
    const uint32_t sB0 = smem_u32(&sm[0][1][0]);
    const uint32_t stgstride = 2 * 128 * 32 * 2;   // bytes between stages

    float acc[4][4][4];
#pragma unroll
    for (int i = 0; i < 4; i++)
#pragma unroll
        for (int j = 0; j < 4; j++)
#pragma unroll
            for (int e = 0; e < 4; e++) acc[i][j][e] = 0.f;

    // Per-thread global->smem chunk coordinates (2 chunks of A, 2 of B)
    const int r0 = tid >> 2,        c0 = tid & 3;          // chunk idx tid
    const int r1 = (tid + 256) >> 2, c1 = (tid + 256) & 3; // chunk idx tid+256
    const uint32_t so0 = swz(r0, c0), so1 = swz(r1, c1);

    // ldmatrix lane addressing (within a 16x16 fragment group)
    const int lrow  = lane & 15;
    const int lksel = lane >> 4;

#define ISSUE(it, stage)                                                      \
    do {                                                                      \
        int _p  = (it) >> 5;                                                  \
        int _kt = (it) & 31;                                                  \
        int _ao = (_p == 1) ? 1024 : 0;                                       \
        int _bo = (_p == 2) ? 1024 : 0;                                       \
        const __nv_bfloat16* _Ag = A2 + (size_t)brow * K2 + _ao + _kt * 32;   \
        const __nv_bfloat16* _Bg = B2 + (size_t)bcol * K2 + _bo + _kt * 32;   \
        uint32_t _sa = sA0 + (stage) * stgstride;                             \
        uint32_t _sb = sB0 + (stage) * stgstride;                             \
        cp_async16(_sa + so0, _Ag + (size_t)r0 * K2 + c0 * 8);                \
        cp_async16(_sa + so1, _Ag + (size_t)r1 * K2 + c1 * 8);                \
        cp_async16(_sb + so0, _Bg + (size_t)r0 * K2 + c0 * 8);                \
        cp_async16(_sb + so1, _Bg + (size_t)r1 * K2 + c1 * 8);                \
        cp_commit();                                                          \
    } while (0)

    ISSUE(0, 0);

    for (int it = 0; it < NITER; it++) {
        const int cur = it & 1;
        if (it + 1 < NITER) {
            ISSUE(it + 1, cur ^ 1);
            cp_wait<1>();
        } else {
            cp_wait<0>();
        }
        __syncthreads();

        const uint32_t sa = sA0 + cur * stgstride;
        const uint32_t sb = sB0 + cur * stgstride;

#pragma unroll
        for (int ks = 0; ks < 2; ks++) {
            uint32_t a[4][4], b[4][2];
#pragma unroll
            for (int mi = 0; mi < 4; mi++) {
                int row   = wm * 64 + mi * 16 + lrow;
                int chunk = ks * 2 + lksel;
                ldsm_x4(a[mi][0], a[mi][1], a[mi][2], a[mi][3],
                        sa + swz(row, chunk));
            }
#pragma unroll
            for (int nj = 0; nj < 2; nj++) {
                int row   = wn * 32 + nj * 16 + lrow;
                int chunk = ks * 2 + lksel;
                uint32_t t0, t1, t2, t3;
                ldsm_x4(t0, t1, t2, t3, sb + swz(row, chunk));
                b[nj * 2 + 0][0] = t0;  b[nj * 2 + 1][0] = t1;
                b[nj * 2 + 0][1] = t2;  b[nj * 2 + 1][1] = t3;
            }
#pragma unroll
            for (int mi = 0; mi < 4; mi++)
#pragma unroll
                for (int ni = 0; ni < 4; ni++)
                    mma_bf16(acc[mi][ni], a[mi], b[ni]);
        }
        __syncthreads();
    }
#undef ISSUE

    // Epilogue: add bias, fp32 float2 stores.
#pragma unroll
    for (int mi = 0; mi < 4; mi++) {
#pragma unroll
        for (int ni = 0; ni < 4; ni++) {
            int r = brow + wm * 64 + mi * 16 + (lane >> 2);
            int c = bcol + wn * 32 + ni * 8 + (lane & 3) * 2;
            float bx = bias[c], by = bias[c + 1];
            float2 v0 = make_float2(acc[mi][ni][0] + bx, acc[mi][ni][1] + by);
            float2 v1 = make_float2(acc[mi][ni][2] + bx, acc[mi][ni][3] + by);
            *(float2*)(C + (size_t)r * N + c)       = v0;
            *(float2*)(C + (size_t)(r + 8) * N + c) = v1;
        }
    }
}

// ---------------------------------------------------------------------------
// Flash-style attention (fp32 math, vectorized smem access).
// Emits bf16 hi/lo split directly into g_attb for the final tensor-core GEMM.
// ---------------------------------------------------------------------------
__global__ __launch_bounds__(256) void attn_kernel(
    const float* __restrict__ Q, const float* __restrict__ K,
    const float* __restrict__ V, const int* __restrict__ masks)
{
    __shared__ float Qts[DKdim][68];   // [d][q], rows 272B (16B-aligned)
    __shared__ float Kts[DKdim][36];   // [d][k], rows 144B (8B-aligned)
    __shared__ float Vs [32][68];      // [k][d]
    __shared__ float Pts[32][68];      // [k][q]
    __shared__ int   msk[32];

    const int tid = threadIdx.x;
    const int tx  = tid & 15;
    const int ty  = tid >> 4;
    const int b   = blockIdx.z, h = blockIdx.y;
    const int q0  = blockIdx.x * 64;

    const float* Qb = Q + ((size_t)(b * Sdim + q0)) * Ddim + h * DKdim;
    const float* Kb = K + ((size_t)b * Sdim) * Ddim + h * DKdim;
    const float* Vb = V + ((size_t)b * Sdim) * Ddim + h * DKdim;

    // Load Q tile (64 q x 64 d), transposed + pre-scaled by 1/sqrt(DK)
#pragma unroll
    for (int i = 0; i < 4; i++) {
        int idx = tid + i * 256;
        int q   = idx >> 4;
        int dv  = idx & 15;
        float4 v = *(const float4*)(Qb + (size_t)q * Ddim + dv * 4);
        Qts[dv * 4 + 0][q] = v.x * 0.125f;
        Qts[dv * 4 + 1][q] = v.y * 0.125f;
        Qts[dv * 4 + 2][q] = v.z * 0.125f;
        Qts[dv * 4 + 3][q] = v.w * 0.125f;
    }

    float m_i[4], l_i[4], o[4][4];
#pragma unroll
    for (int i = 0; i < 4; i++) {
        m_i[i] = -1e30f; l_i[i] = 0.f;
#pragma unroll
        for (int j = 0; j < 4; j++) o[i][j] = 0.f;
    }

    for (int t = 0; t < Sdim / 32; t++) {
        const int kb = t * 32;
        __syncthreads();

        // Load K (transposed) and V (row-major) tiles
#pragma unroll
        for (int i = 0; i < 2; i++) {
            int idx = tid + i * 256;
            int k   = idx >> 4;
            int dv  = idx & 15;
            float4 kv = *(const float4*)(Kb + (size_t)(kb + k) * Ddim + dv * 4);
            Kts[dv * 4 + 0][k] = kv.x;
            Kts[dv * 4 + 1][k] = kv.y;
            Kts[dv * 4 + 2][k] = kv.z;
            Kts[dv * 4 + 3][k] = kv.w;
            *(float4*)&Vs[k][dv * 4] =
                *(const float4*)(Vb + (size_t)(kb + k) * Ddim + dv * 4);
        }
        if (tid < 32) msk[tid] = masks[b * Sdim + kb + tid];
        __syncthreads();

        // Scores: s[4 queries][2 keys] — vectorized smem reads
        float s[4][2] = {{0.f, 0.f}, {0.f, 0.f}, {0.f, 0.f}, {0.f, 0.f}};
#pragma unroll 8
        for (int d = 0; d < DKdim; d++) {
            float4 a  = *(const float4*)&Qts[d][ty * 4];
            float2 bk = *(const float2*)&Kts[d][tx * 2];
            s[0][0] += a.x * bk.x;  s[0][1] += a.x * bk.y;
            s[1][0] += a.y * bk.x;  s[1][1] += a.y * bk.y;
            s[2][0] += a.z * bk.x;  s[2][1] += a.z * bk.y;
            s[3][0] += a.w * bk.x;  s[3][1] += a.w * bk.y;
        }
#pragma unroll
        for (int j = 0; j < 2; j++) {
            if (msk[tx * 2 + j] == 0) {
#pragma unroll
                for (int i = 0; i < 4; i++) s[i][j] = -1e9f;
            }
        }

        // Online softmax update (16 tx lanes share each query row)
#pragma unroll
        for (int i = 0; i < 4; i++) {
            float tmax = fmaxf(s[i][0], s[i][1]);
#pragma unroll
            for (int off = 8; off; off >>= 1)
                tmax = fmaxf(tmax, __shfl_xor_sync(0xffffffffu, tmax, off));
            float nm   = fmaxf(m_i[i], tmax);
            float corr = __expf(m_i[i] - nm);
            float p0   = __expf(s[i][0] - nm);
            float p1   = __expf(s[i][1] - nm);
            float ts   = p0 + p1;
#pragma unroll
            for (int off = 8; off; off >>= 1)
                ts += __shfl_xor_sync(0xffffffffu, ts, off);
            l_i[i] = l_i[i] * corr + ts;
            m_i[i] = nm;
#pragma unroll
            for (int j = 0; j < 4; j++) o[i][j] *= corr;
            Pts[tx * 2 + 0][ty * 4 + i] = p0;
            Pts[tx * 2 + 1][ty * 4 + i] = p1;
        }
        __syncthreads();

        // O += P * V — vectorized smem reads
#pragma unroll 8
        for (int k = 0; k < 32; k++) {
            float4 a  = *(const float4*)&Pts[k][ty * 4];
            float4 bv = *(const float4*)&Vs[k][tx * 4];
            o[0][0] += a.x * bv.x;  o[0][1] += a.x * bv.y;  o[0][2] += a.x * bv.z;  o[0][3] += a.x * bv.w;
            o[1][0] += a.y * bv.x;  o[1][1] += a.y * bv.y;  o[1][2] += a.y * bv.z;  o[1][3] += a.y * bv.w;
            o[2][0] += a.z * bv.x;  o[2][1] += a.z * bv.y;  o[2][2] += a.z * bv.z;  o[2][3] += a.z * bv.w;
            o[3][0] += a.w * bv.x;  o[3][1] += a.w * bv.y;  o[3][2] += a.w * bv.z;  o[3][3] += a.w * bv.w;
        }
    }

    // Normalize + write bf16 hi/lo split into g_attb [M, 2048]
#pragma unroll
    for (int i = 0; i < 4; i++) {
        float inv = 1.0f / l_i[i];
        float vv[4];
#pragma unroll
        for (int j = 0; j < 4; j++) vv[j] = o[i][j] * inv;
        int row = b * Sdim + q0 + ty * 4 + i;
        int col = h * DKdim + tx * 4;
        __nv_bfloat16 hb[4], lb[4];
#pragma unroll
        for (int j = 0; j < 4; j++) {
            hb[j] = __float2bfloat16(vv[j]);
            lb[j] = __float2bfloat16(vv[j] - __bfloat162float(hb[j]));
        }
        uint2 ph, pl;
        ph.x = bfpack(hb[0], hb[1]); ph.y = bfpack(hb[2], hb[3]);
        pl.x = bfpack(lb[0], lb[1]); pl.y = bfpack(lb[2], lb[3]);
        *(uint2*)(&g_attb[(size_t)row * K2 + col])        = ph;
        *(uint2*)(&g_attb[(size_t)row * K2 + 1024 + col]) = pl;
    }
}

// ---------------------------------------------------------------------------
// kernel_launch: graph-capturable, allocation-free.
// Input order: x, masks, Wq, bq, Wk, bk, Wv, bv, Wo, bo
// ---------------------------------------------------------------------------
extern "C" void kernel_launch(void* const* d_in, const int* in_sizes, int n_in,
                              void* d_out, int out_size)
{
    const float* x     = (const float*)d_in[0];
    const int*   masks = (const int*)  d_in[1];
    const float* Wq    = (const float*)d_in[2];
    const float* bq    = (const float*)d_in[3];
    const float* Wk    = (const float*)d_in[4];
    const float* bk    = (const float*)d_in[5];
    const float* Wv    = (const float*)d_in[6];
    const float* bv    = (const float*)d_in[7];
    const float* Wo    = (const float*)d_in[8];
    const float* bo    = (const float*)d_in[9];
    float* out = (float*)d_out;

    __nv_bfloat16 *xs, *wq2, *wk2, *wv2, *wo2, *attb;
    float *q, *k, *v;
    cudaGetSymbolAddress((void**)&xs,   g_xs);
    cudaGetSymbolAddress((void**)&wq2,  g_wq);
    cudaGetSymbolAddress((void**)&wk2,  g_wk);
    cudaGetSymbolAddress((void**)&wv2,  g_wv);
    cudaGetSymbolAddress((void**)&wo2,  g_wo);
    cudaGetSymbolAddress((void**)&q,    g_q);
    cudaGetSymbolAddress((void**)&k,    g_k);
    cudaGetSymbolAddress((void**)&v,    g_v);
    cudaGetSymbolAddress((void**)&attb, g_attb);

    // fp32 -> bf16 hi/lo conversions
    split_x_kernel<<<(Mdim * Ddim) / 4 / 256, 256>>>(x, xs);
    dim3 wgrid(32, 32), wblk(32, 8);
    wsplit_kernel<<<wgrid, wblk>>>(Wq, wq2);
    wsplit_kernel<<<wgrid, wblk>>>(Wk, wk2);
    wsplit_kernel<<<wgrid, wblk>>>(Wv, wv2);
    wsplit_kernel<<<wgrid, wblk>>>(Wo, wo2);

    // Projections via mma.sync bf16-split GEMM
    dim3 gg(Ddim / 128, Mdim / 128);   // (8, 64)
    gemm_mma<<<gg, 256>>>(xs, wq2, bq, q, Ddim);
    gemm_mma<<<gg, 256>>>(xs, wk2, bk, k, Ddim);
    gemm_mma<<<gg, 256>>>(xs, wv2, bv, v, Ddim);

    // Attention (fp32) -> bf16 split output
    dim3 ga(Sdim / 64, Hdim, Bdim);    // (16, 16, 8)
    attn_kernel<<<ga, 256>>>(q, k, v, masks);

    // Output projection
    gemm_mma<<<gg, 256>>>(attb, wo2, bo, out, Ddim);
}

// round 12
// speedup vs baseline: 2.7834x; 1.7932x over previous
#include <cuda_runtime.h>
#include <cuda_bf16.h>
#include <cstdint>

// Problem dims (fixed by the reference)
#define Bdim  8
#define Sdim  1024
#define Ddim  1024
#define Hdim  16
#define DKdim 64
#define Mdim  (Bdim * Sdim)   // 8192 rows
#define K2    2048            // split width (hi | lo)

// ---------------------------------------------------------------------------
// Scratch (__device__ globals; no cudaMalloc allowed)
// ---------------------------------------------------------------------------
__device__ __nv_bfloat16 g_xs  [(size_t)Mdim * K2];   // x split    [M,2048]
__device__ __nv_bfloat16 g_wq  [(size_t)Ddim * K2];   // Wq^T split [N,2048]
__device__ __nv_bfloat16 g_wk  [(size_t)Ddim * K2];
__device__ __nv_bfloat16 g_wv  [(size_t)Ddim * K2];
__device__ __nv_bfloat16 g_wo  [(size_t)Ddim * K2];
__device__ __nv_bfloat16 g_qs  [(size_t)Mdim * K2];   // Q split (pre-scaled 1/8)
__device__ __nv_bfloat16 g_ks  [(size_t)Mdim * K2];   // K split
__device__ __nv_bfloat16 g_vs  [(size_t)Mdim * K2];   // V split
__device__ __nv_bfloat16 g_attb[(size_t)Mdim * K2];   // attn out split

// ---------------------------------------------------------------------------
// Helpers (arch-agnostic PTX only: cp.async, ldmatrix, mma.sync)
// ---------------------------------------------------------------------------
__device__ __forceinline__ uint32_t smem_u32(const void* p) {
    uint32_t a;
    asm("{ .reg .u64 t; cvta.to.shared.u64 t, %1; cvt.u32.u64 %0, t; }"
        : "=r"(a) : "l"(p));
    return a;
}

__device__ __forceinline__ void cp_async16(uint32_t dst, const void* src) {
    asm volatile("cp.async.cg.shared.global [%0], [%1], 16;"
                 :: "r"(dst), "l"(src) : "memory");
}
__device__ __forceinline__ void cp_commit() {
    asm volatile("cp.async.commit_group;" ::: "memory");
}
template <int N>
__device__ __forceinline__ void cp_wait() {
    asm volatile("cp.async.wait_group %0;" :: "n"(N) : "memory");
}

__device__ __forceinline__ void ldsm_x4(uint32_t& r0, uint32_t& r1,
                                        uint32_t& r2, uint32_t& r3, uint32_t a) {
    asm volatile("ldmatrix.sync.aligned.m8n8.x4.shared.b16 {%0,%1,%2,%3}, [%4];"
                 : "=r"(r0), "=r"(r1), "=r"(r2), "=r"(r3) : "r"(a));
}
__device__ __forceinline__ void ldsm_x4_t(uint32_t& r0, uint32_t& r1,
                                          uint32_t& r2, uint32_t& r3, uint32_t a) {
    asm volatile("ldmatrix.sync.aligned.m8n8.x4.trans.shared.b16 {%0,%1,%2,%3}, [%4];"
                 : "=r"(r0), "=r"(r1), "=r"(r2), "=r"(r3) : "r"(a));
}

__device__ __forceinline__ void mma_bf16(float* d, const uint32_t* a,
                                         const uint32_t* b) {
    asm volatile(
        "mma.sync.aligned.m16n8k16.row.col.f32.bf16.bf16.f32 "
        "{%0,%1,%2,%3}, {%4,%5,%6,%7}, {%8,%9}, {%0,%1,%2,%3};"
        : "+f"(d[0]), "+f"(d[1]), "+f"(d[2]), "+f"(d[3])
        : "r"(a[0]), "r"(a[1]), "r"(a[2]), "r"(a[3]), "r"(b[0]), "r"(b[1]));
}

__device__ __forceinline__ uint32_t bfpack(__nv_bfloat16 a, __nv_bfloat16 b) {
    return ((uint32_t)__bfloat16_as_ushort(b) << 16) | (uint32_t)__bfloat16_as_ushort(a);
}

// Pack (x,y) -> bf16x2 hi-plane + residual lo-plane (x in low half).
#define SPLITPK(dh, dl, x, y)                                                  \
    {                                                                          \
        float _x = (x), _y = (y);                                              \
        __nv_bfloat16 _hx = __float2bfloat16(_x), _hy = __float2bfloat16(_y);  \
        (dh) = bfpack(_hx, _hy);                                               \
        (dl) = bfpack(__float2bfloat16(_x - __bfloat162float(_hx)),            \
                      __float2bfloat16(_y - __bfloat162float(_hy)));           \
    }

// Swizzle inside a [rows x 32 bf16] tile (64B rows, 4 chunks)
__device__ __forceinline__ uint32_t swz(int row, int chunk) {
    return (uint32_t)(row * 64 + ((chunk ^ ((row >> 1) & 3)) << 4));
}
// Swizzle inside a [rows x 64 bf16] tile (128B rows, 8 chunks)
__device__ __forceinline__ uint32_t sw64o(int row, int chunk) {
    return (uint32_t)(row * 128 + ((chunk ^ (row & 7)) << 4));
}

// ---------------------------------------------------------------------------
// Conversion kernels
// ---------------------------------------------------------------------------
__global__ __launch_bounds__(256) void split_x_kernel(const float* __restrict__ X,
                                                      __nv_bfloat16* __restrict__ Y) {
    size_t t = (size_t)blockIdx.x * 256 + threadIdx.x;
    size_t e = t * 4;
    int row = (int)(e >> 10);
    int col = (int)(e & 1023);
    float4 v = *(const float4*)(X + e);
    float vv[4] = {v.x, v.y, v.z, v.w};
    __nv_bfloat16 h[4], l[4];
#pragma unroll
    for (int j = 0; j < 4; j++) {
        h[j] = __float2bfloat16(vv[j]);
        l[j] = __float2bfloat16(vv[j] - __bfloat162float(h[j]));
    }
    uint2 ph, pl;
    ph.x = bfpack(h[0], h[1]); ph.y = bfpack(h[2], h[3]);
    pl.x = bfpack(l[0], l[1]); pl.y = bfpack(l[2], l[3]);
    *(uint2*)(Y + (size_t)row * K2 + col)        = ph;
    *(uint2*)(Y + (size_t)row * K2 + 1024 + col) = pl;
}

__global__ __launch_bounds__(256) void wsplit_kernel(const float* __restrict__ W,
                                                     __nv_bfloat16* __restrict__ Y) {
    __shared__ float t[32][33];
    int k0 = blockIdx.x * 32, n0 = blockIdx.y * 32;
    int tx = threadIdx.x, ty = threadIdx.y;   // 32 x 8
#pragma unroll
    for (int i = 0; i < 4; i++)
        t[ty + 8 * i][tx] = W[(size_t)(k0 + ty + 8 * i) * 1024 + n0 + tx];
    __syncthreads();
#pragma unroll
    for (int i = 0; i < 4; i++) {
        int n = n0 + ty + 8 * i;
        float v = t[tx][ty + 8 * i];
        __nv_bfloat16 h = __float2bfloat16(v);
        __nv_bfloat16 l = __float2bfloat16(v - __bfloat162float(h));
        Y[(size_t)n * K2 + k0 + tx]        = h;
        Y[(size_t)n * K2 + 1024 + k0 + tx] = l;
    }
}

// ---------------------------------------------------------------------------
// bf16-split GEMM via mma.sync.
// C = (A·B^T + bias) * scale.  Output either fp32 [M,N] (Cf) or
// bf16 hi/lo split [M,2048] (Cs).  3 passes x 32 K-chunks = 96 iters.
// ---------------------------------------------------------------------------
#define NITER 96

__global__ __launch_bounds__(256) void gemm_mma(
    const __nv_bfloat16* __restrict__ A2,
    const __nv_bfloat16* __restrict__ B2,
    const float* __restrict__ bias,
    float* __restrict__ Cf,
    __nv_bfloat16* __restrict__ Cs,
    float scale, int N)
{
    __shared__ __align__(128) __nv_bfloat16 sm[2][2][128 * 32];

    const int tid  = threadIdx.x;
    const int lane = tid & 31;
    const int warp = tid >> 5;
    const int wm   = warp & 1;
    const int wn   = warp >> 1;
    const int brow = blockIdx.y * 128;
    const int bcol = blockIdx.x * 128;

    const uint32_t sA0 = smem_u32(&sm[0][0][0]);
    const uint32_t sB0 = smem_u32(&sm[0][1][0]);
    const uint32_t stgstride = 2 * 128 * 32 * 2;

    float acc[4][4][4];
#pragma unroll
    for (int i = 0; i < 4; i++)
#pragma unroll
        for (int j = 0; j < 4; j++)
#pragma unroll
            for (int e = 0; e < 4; e++) acc[i][j][e] = 0.f;

    const int r0 = tid >> 2,         c0 = tid & 3;
    const int r1 = (tid + 256) >> 2, c1 = (tid + 256) & 3;
    const uint32_t so0 = swz(r0, c0), so1 = swz(r1, c1);

    const int lrow  = lane & 15;
    const int lksel = lane >> 4;

#define ISSUE(it, stage)                                                      \
    do {                                                                      \
        int _p  = (it) >> 5;                                                  \
        int _kt = (it) & 31;                                                  \
        int _ao = (_p == 1) ? 1024 : 0;                                       \
        int _bo = (_p == 2) ? 1024 : 0;                                       \
        const __nv_bfloat16* _Ag = A2 + (size_t)brow * K2 + _ao + _kt * 32;   \
        const __nv_bfloat16* _Bg = B2 + (size_t)bcol * K2 + _bo + _kt * 32;   \
        uint32_t _sa = sA0 + (stage) * stgstride;                             \
        uint32_t _sb = sB0 + (stage) * stgstride;                             \
        cp_async16(_sa + so0, _Ag + (size_t)r0 * K2 + c0 * 8);                \
        cp_async16(_sa + so1, _Ag + (size_t)r1 * K2 + c1 * 8);                \
        cp_async16(_sb + so0, _Bg + (size_t)r0 * K2 + c0 * 8);                \
        cp_async16(_sb + so1, _Bg + (size_t)r1 * K2 + c1 * 8);                \
        cp_commit();                                                          \
    } while (0)

    ISSUE(0, 0);

    for (int it = 0; it < NITER; it++) {
        const int cur = it & 1;
        if (it + 1 < NITER) {
            ISSUE(it + 1, cur ^ 1);
            cp_wait<1>();
        } else {
            cp_wait<0>();
        }
        __syncthreads();

        const uint32_t sa = sA0 + cur * stgstride;
        const uint32_t sb = sB0 + cur * stgstride;

#pragma unroll
        for (int ks = 0; ks < 2; ks++) {
            uint32_t a[4][4], b[4][2];
#pragma unroll
            for (int mi = 0; mi < 4; mi++) {
                int row   = wm * 64 + mi * 16 + lrow;
                int chunk = ks * 2 + lksel;
                ldsm_x4(a[mi][0], a[mi][1], a[mi][2], a[mi][3],
                        sa + swz(row, chunk));
            }
#pragma unroll
            for (int nj = 0; nj < 2; nj++) {
                int row   = wn * 32 + nj * 16 + lrow;
                int chunk = ks * 2 + lksel;
                uint32_t t0, t1, t2, t3;
                ldsm_x4(t0, t1, t2, t3, sb + swz(row, chunk));
                b[nj * 2 + 0][0] = t0;  b[nj * 2 + 1][0] = t1;
                b[nj * 2 + 0][1] = t2;  b[nj * 2 + 1][1] = t3;
            }
#pragma unroll
            for (int mi = 0; mi < 4; mi++)
#pragma unroll
                for (int ni = 0; ni < 4; ni++)
                    mma_bf16(acc[mi][ni], a[mi], b[ni]);
        }
        __syncthreads();
    }
#undef ISSUE

    // Epilogue
#pragma unroll
    for (int mi = 0; mi < 4; mi++) {
#pragma unroll
        for (int ni = 0; ni < 4; ni++) {
            int r = brow + wm * 64 + mi * 16 + (lane >> 2);
            int c = bcol + wn * 32 + ni * 8 + (lane & 3) * 2;
            float bx = bias[c], by = bias[c + 1];
            float x0 = (acc[mi][ni][0] + bx) * scale;
            float x1 = (acc[mi][ni][1] + by) * scale;
            float x2 = (acc[mi][ni][2] + bx) * scale;
            float x3 = (acc[mi][ni][3] + by) * scale;
            if (Cs) {
                uint32_t h01, l01, h23, l23;
                SPLITPK(h01, l01, x0, x1);
                SPLITPK(h23, l23, x2, x3);
                *(uint32_t*)(Cs + (size_t)r * K2 + c)              = h01;
                *(uint32_t*)(Cs + (size_t)r * K2 + 1024 + c)       = l01;
                *(uint32_t*)(Cs + (size_t)(r + 8) * K2 + c)        = h23;
                *(uint32_t*)(Cs + (size_t)(r + 8) * K2 + 1024 + c) = l23;
            } else {
                *(float2*)(Cf + (size_t)r * N + c)       = make_float2(x0, x1);
                *(float2*)(Cf + (size_t)(r + 8) * N + c) = make_float2(x2, x3);
            }
        }
    }
}

// ---------------------------------------------------------------------------
// Tensor-core flash attention (mma.sync bf16, 3-term split on both matmuls).
// CTA = 64 queries of one (b,h); 4 warps x 16 q-rows; 16 key-tiles of 64.
// smem: 2 stages x (Khi|Klo|Vhi|Vlo, 8KB each) + masks.
// ---------------------------------------------------------------------------
#define ATTN_SMEM (65536 + 512)

__global__ __launch_bounds__(128) void attn_mma(
    const __nv_bfloat16* __restrict__ Qs,
    const __nv_bfloat16* __restrict__ Ks,
    const __nv_bfloat16* __restrict__ Vsrc,
    const int* __restrict__ masks,
    __nv_bfloat16* __restrict__ Ob)
{
    extern __shared__ char smraw[];
    const uint32_t sb = smem_u32(smraw);
    int* mskp = (int*)(smraw + 65536);

    const int tid  = threadIdx.x;
    const int lane = tid & 31;
    const int warp = tid >> 5;
    const int lrow  = lane & 15;
    const int lksel = lane >> 4;
    const int b = blockIdx.z, h = blockIdx.y;
    const int q0 = blockIdx.x * 64;

    const __nv_bfloat16* Qg = Qs   + (size_t)(b * Sdim + q0) * K2 + h * 64;
    const __nv_bfloat16* Kg = Ks   + (size_t)(b * Sdim) * K2 + h * 64;
    const __nv_bfloat16* Vg = Vsrc + (size_t)(b * Sdim) * K2 + h * 64;

    // ---- stage Q (hi/lo) through smem, extract fragments into registers ----
#pragma unroll
    for (int i = 0; i < 4; i++) {
        int idx = tid + i * 128;      // 512 chunks of 16B
        int r = idx >> 3, c = idx & 7;
        uint32_t off = sw64o(r, c);
        cp_async16(sb + off,        Qg + (size_t)r * K2 + c * 8);
        cp_async16(sb + 8192 + off, Qg + (size_t)r * K2 + 1024 + c * 8);
    }
    cp_commit();
    cp_wait<0>();
    __syncthreads();

    uint32_t aqh[4][4], aql[4][4];
#pragma unroll
    for (int ks = 0; ks < 4; ks++) {
        uint32_t off = sw64o(warp * 16 + lrow, ks * 2 + lksel);
        ldsm_x4(aqh[ks][0], aqh[ks][1], aqh[ks][2], aqh[ks][3], sb + off);
        ldsm_x4(aql[ks][0], aql[ks][1], aql[ks][2], aql[ks][3], sb + 8192 + off);
    }
    __syncthreads();

#define AISSUE(kt, stg)                                                         \
    do {                                                                        \
        const __nv_bfloat16* _K = Kg + (size_t)(kt) * 64 * K2;                  \
        const __nv_bfloat16* _V = Vg + (size_t)(kt) * 64 * K2;                  \
        uint32_t _s = sb + (stg) * 32768;                                       \
        _Pragma("unroll")                                                       \
        for (int _i = 0; _i < 4; _i++) {                                        \
            int _idx = tid + _i * 128;                                          \
            int _r = _idx >> 3, _c = _idx & 7;                                  \
            uint32_t _o = sw64o(_r, _c);                                        \
            cp_async16(_s + _o,         _K + (size_t)_r * K2 + _c * 8);         \
            cp_async16(_s + 8192 + _o,  _K + (size_t)_r * K2 + 1024 + _c * 8);  \
            cp_async16(_s + 16384 + _o, _V + (size_t)_r * K2 + _c * 8);         \
            cp_async16(_s + 24576 + _o, _V + (size_t)_r * K2 + 1024 + _c * 8);  \
        }                                                                       \
        if (tid < 64) mskp[(stg) * 64 + tid] = masks[b * Sdim + (kt) * 64 + tid]; \
        cp_commit();                                                            \
    } while (0)

    float m0 = -1e30f, m1 = -1e30f, l0 = 0.f, l1 = 0.f;
    float o[8][4];
#pragma unroll
    for (int dt = 0; dt < 8; dt++)
#pragma unroll
        for (int e = 0; e < 4; e++) o[dt][e] = 0.f;

    AISSUE(0, 0);

    for (int kt = 0; kt < 16; kt++) {
        const int st = kt & 1;
        if (kt + 1 < 16) {
            AISSUE(kt + 1, st ^ 1);
            cp_wait<1>();
        } else {
            cp_wait<0>();
        }
        __syncthreads();

        const uint32_t sK  = sb + st * 32768;
        const uint32_t sKl = sK + 8192;
        const uint32_t sV  = sK + 16384;
        const uint32_t sVl = sK + 24576;
        const int* mk = mskp + st * 64;

        // -------- scores: S = Qhi*Khi + Qlo*Khi + Qhi*Klo --------
        float sc[8][4];
#pragma unroll
        for (int nt = 0; nt < 8; nt++)
#pragma unroll
            for (int e = 0; e < 4; e++) sc[nt][e] = 0.f;

#pragma unroll
        for (int ks = 0; ks < 4; ks++) {
            uint32_t bk[8][2];
#pragma unroll
            for (int np = 0; np < 4; np++) {
                uint32_t t0, t1, t2, t3;
                ldsm_x4(t0, t1, t2, t3, sK + sw64o(np * 16 + lrow, ks * 2 + lksel));
                bk[np * 2][0] = t0;  bk[np * 2][1] = t2;
                bk[np * 2 + 1][0] = t1;  bk[np * 2 + 1][1] = t3;
            }
#pragma unroll
            for (int nt = 0; nt < 8; nt++) mma_bf16(sc[nt], aqh[ks], bk[nt]);
#pragma unroll
            for (int nt = 0; nt < 8; nt++) mma_bf16(sc[nt], aql[ks], bk[nt]);
#pragma unroll
            for (int np = 0; np < 4; np++) {
                uint32_t t0, t1, t2, t3;
                ldsm_x4(t0, t1, t2, t3, sKl + sw64o(np * 16 + lrow, ks * 2 + lksel));
                bk[np * 2][0] = t0;  bk[np * 2][1] = t2;
                bk[np * 2 + 1][0] = t1;  bk[np * 2 + 1][1] = t3;
            }
#pragma unroll
            for (int nt = 0; nt < 8; nt++) mma_bf16(sc[nt], aqh[ks], bk[nt]);
        }

        // -------- mask --------
#pragma unroll
        for (int nt = 0; nt < 8; nt++) {
            int k0 = nt * 8 + 2 * (lane & 3);
            if (mk[k0] == 0)     { sc[nt][0] = -1e9f; sc[nt][2] = -1e9f; }
            if (mk[k0 + 1] == 0) { sc[nt][1] = -1e9f; sc[nt][3] = -1e9f; }
        }

        // -------- online softmax (rows r = lane>>2 and r+8) --------
        float mx0 = -1e30f, mx1 = -1e30f;
#pragma unroll
        for (int nt = 0; nt < 8; nt++) {
            mx0 = fmaxf(mx0, fmaxf(sc[nt][0], sc[nt][1]));
            mx1 = fmaxf(mx1, fmaxf(sc[nt][2], sc[nt][3]));
        }
        mx0 = fmaxf(mx0, __shfl_xor_sync(0xffffffffu, mx0, 1));
        mx0 = fmaxf(mx0, __shfl_xor_sync(0xffffffffu, mx0, 2));
        mx1 = fmaxf(mx1, __shfl_xor_sync(0xffffffffu, mx1, 1));
        mx1 = fmaxf(mx1, __shfl_xor_sync(0xffffffffu, mx1, 2));

        float nm0 = fmaxf(m0, mx0), nm1 = fmaxf(m1, mx1);
        float cr0 = __expf(m0 - nm0), cr1 = __expf(m1 - nm1);
        float s0 = 0.f, s1 = 0.f;
#pragma unroll
        for (int nt = 0; nt < 8; nt++) {
            sc[nt][0] = __expf(sc[nt][0] - nm0);  s0 += sc[nt][0];
            sc[nt][1] = __expf(sc[nt][1] - nm0);  s0 += sc[nt][1];
            sc[nt][2] = __expf(sc[nt][2] - nm1);  s1 += sc[nt][2];
            sc[nt][3] = __expf(sc[nt][3] - nm1);  s1 += sc[nt][3];
        }
        s0 += __shfl_xor_sync(0xffffffffu, s0, 1);
        s0 += __shfl_xor_sync(0xffffffffu, s0, 2);
        s1 += __shfl_xor_sync(0xffffffffu, s1, 1);
        s1 += __shfl_xor_sync(0xffffffffu, s1, 2);
        l0 = l0 * cr0 + s0;  l1 = l1 * cr1 + s1;
        m0 = nm0;  m1 = nm1;
#pragma unroll
        for (int dt = 0; dt < 8; dt++) {
            o[dt][0] *= cr0;  o[dt][1] *= cr0;
            o[dt][2] *= cr1;  o[dt][3] *= cr1;
        }

        // -------- O += Phi*Vhi + Plo*Vhi + Phi*Vlo --------
#pragma unroll
        for (int ks = 0; ks < 4; ks++) {
            uint32_t ah[4], al[4];
            SPLITPK(ah[0], al[0], sc[2 * ks][0],     sc[2 * ks][1]);
            SPLITPK(ah[1], al[1], sc[2 * ks][2],     sc[2 * ks][3]);
            SPLITPK(ah[2], al[2], sc[2 * ks + 1][0], sc[2 * ks + 1][1]);
            SPLITPK(ah[3], al[3], sc[2 * ks + 1][2], sc[2 * ks + 1][3]);

            uint32_t bv[8][2];
#pragma unroll
            for (int dp = 0; dp < 4; dp++) {
                uint32_t t0, t1, t2, t3;
                ldsm_x4_t(t0, t1, t2, t3, sV + sw64o(ks * 16 + lrow, dp * 2 + lksel));
                bv[dp * 2][0] = t0;  bv[dp * 2][1] = t1;
                bv[dp * 2 + 1][0] = t2;  bv[dp * 2 + 1][1] = t3;
            }
#pragma unroll
            for (int dt = 0; dt < 8; dt++) mma_bf16(o[dt], ah, bv[dt]);
#pragma unroll
            for (int dt = 0; dt < 8; dt++) mma_bf16(o[dt], al, bv[dt]);
#pragma unroll
            for (int dp = 0; dp < 4; dp++) {
                uint32_t t0, t1, t2, t3;
                ldsm_x4_t(t0, t1, t2, t3, sVl + sw64o(ks * 16 + lrow, dp * 2 + lksel));
                bv[dp * 2][0] = t0;  bv[dp * 2][1] = t1;
                bv[dp * 2 + 1][0] = t2;  bv[dp * 2 + 1][1] = t3;
            }
#pragma unroll
            for (int dt = 0; dt < 8; dt++) mma_bf16(o[dt], ah, bv[dt]);
        }
        __syncthreads();
    }
#undef AISSUE

    // -------- normalize + write bf16 hi/lo split --------
    float i0 = 1.f / l0, i1 = 1.f / l1;
    int rg = b * Sdim + q0 + warp * 16 + (lane >> 2);
    int cb = h * 64 + 2 * (lane & 3);
    __nv_bfloat16* O0 = Ob + (size_t)rg * K2;
    __nv_bfloat16* O1 = Ob + (size_t)(rg + 8) * K2;
#pragma unroll
    for (int dt = 0; dt < 8; dt++) {
        int c = cb + dt * 8;
        uint32_t h01, l01, h23, l23;
        SPLITPK(h01, l01, o[dt][0] * i0, o[dt][1] * i0);
        SPLITPK(h23, l23, o[dt][2] * i1, o[dt][3] * i1);
        *(uint32_t*)(O0 + c)        = h01;
        *(uint32_t*)(O0 + 1024 + c) = l01;
        *(uint32_t*)(O1 + c)        = h23;
        *(uint32_t*)(O1 + 1024 + c) = l23;
    }
}

// ---------------------------------------------------------------------------
// kernel_launch: graph-capturable, allocation-free.
// Input order: x, masks, Wq, bq, Wk, bk, Wv, bv, Wo, bo
// ---------------------------------------------------------------------------
extern "C" void kernel_launch(void* const* d_in, const int* in_sizes, int n_in,
                              void* d_out, int out_size)
{
    const float* x     = (const float*)d_in[0];
    const int*   masks = (const int*)  d_in[1];
    const float* Wq    = (const float*)d_in[2];
    const float* bq    = (const float*)d_in[3];
    const float* Wk    = (const float*)d_in[4];
    const float* bk    = (const float*)d_in[5];
    const float* Wv    = (const float*)d_in[6];
    const float* bv    = (const float*)d_in[7];
    const float* Wo    = (const float*)d_in[8];
    const float* bo    = (const float*)d_in[9];
    float* out = (float*)d_out;

    __nv_bfloat16 *xs, *wq2, *wk2, *wv2, *wo2, *qs, *ks, *vs, *attb;
    cudaGetSymbolAddress((void**)&xs,   g_xs);
    cudaGetSymbolAddress((void**)&wq2,  g_wq);
    cudaGetSymbolAddress((void**)&wk2,  g_wk);
    cudaGetSymbolAddress((void**)&wv2,  g_wv);
    cudaGetSymbolAddress((void**)&wo2,  g_wo);
    cudaGetSymbolAddress((void**)&qs,   g_qs);
    cudaGetSymbolAddress((void**)&ks,   g_ks);
    cudaGetSymbolAddress((void**)&vs,   g_vs);
    cudaGetSymbolAddress((void**)&attb, g_attb);

    cudaFuncSetAttribute(attn_mma, cudaFuncAttributeMaxDynamicSharedMemorySize,
                         ATTN_SMEM);

    // fp32 -> bf16 hi/lo conversions
    split_x_kernel<<<(Mdim * Ddim) / 4 / 256, 256>>>(x, xs);
    dim3 wgrid(32, 32), wblk(32, 8);
    wsplit_kernel<<<wgrid, wblk>>>(Wq, wq2);
    wsplit_kernel<<<wgrid, wblk>>>(Wk, wk2);
    wsplit_kernel<<<wgrid, wblk>>>(Wv, wv2);
    wsplit_kernel<<<wgrid, wblk>>>(Wo, wo2);

    // Projections -> bf16 split outputs (Q pre-scaled by 1/sqrt(DK))
    dim3 gg(Ddim / 128, Mdim / 128);   // (8, 64)
    gemm_mma<<<gg, 256>>>(xs, wq2, bq, nullptr, qs, 0.125f, Ddim);
    gemm_mma<<<gg, 256>>>(xs, wk2, bk, nullptr, ks, 1.0f,   Ddim);
    gemm_mma<<<gg, 256>>>(xs, wv2, bv, nullptr, vs, 1.0f,   Ddim);

    // Tensor-core flash attention -> bf16 split
    dim3 ga(Sdim / 64, Hdim, Bdim);    // (16, 16, 8)
    attn_mma<<<ga, 128, ATTN_SMEM>>>(qs, ks, vs, masks, attb);

    // Output projection -> fp32
    gemm_mma<<<gg, 256>>>(attb, wo2, bo, out, nullptr, 1.0f, Ddim);
}

// round 13
// speedup vs baseline: 3.1298x; 1.1244x over previous
#include <cuda_runtime.h>
#include <cuda_bf16.h>
#include <cstdint>

// Problem dims (fixed by the reference)
#define Bdim  8
#define Sdim  1024
#define Ddim  1024
#define Hdim  16
#define DKdim 64
#define Mdim  (Bdim * Sdim)   // 8192 rows
#define K2    2048            // split width (hi | lo)

// ---------------------------------------------------------------------------
// Scratch (__device__ globals; no cudaMalloc allowed)
// ---------------------------------------------------------------------------
__device__ __nv_bfloat16 g_xs  [(size_t)Mdim * K2];        // x split [M,2048]
__device__ __nv_bfloat16 g_wqkv[(size_t)3 * Ddim * K2];    // Wq|Wk|Wv ^T split
__device__ __nv_bfloat16 g_wo  [(size_t)Ddim * K2];        // Wo^T split
__device__ __nv_bfloat16 g_qs  [(size_t)Mdim * K2];        // Q split (pre-scaled)
__device__ __nv_bfloat16 g_ks  [(size_t)Mdim * K2];
__device__ __nv_bfloat16 g_vs  [(size_t)Mdim * K2];
__device__ __nv_bfloat16 g_attb[(size_t)Mdim * K2];        // attn out split

// ---------------------------------------------------------------------------
// Helpers (arch-agnostic PTX only: cp.async, ldmatrix, mma.sync)
// ---------------------------------------------------------------------------
__device__ __forceinline__ uint32_t smem_u32(const void* p) {
    uint32_t a;
    asm("{ .reg .u64 t; cvta.to.shared.u64 t, %1; cvt.u32.u64 %0, t; }"
        : "=r"(a) : "l"(p));
    return a;
}

__device__ __forceinline__ void cp_async16(uint32_t dst, const void* src) {
    asm volatile("cp.async.cg.shared.global [%0], [%1], 16;"
                 :: "r"(dst), "l"(src) : "memory");
}
__device__ __forceinline__ void cp_commit() {
    asm volatile("cp.async.commit_group;" ::: "memory");
}
template <int N>
__device__ __forceinline__ void cp_wait() {
    asm volatile("cp.async.wait_group %0;" :: "n"(N) : "memory");
}

__device__ __forceinline__ void ldsm_x4(uint32_t& r0, uint32_t& r1,
                                        uint32_t& r2, uint32_t& r3, uint32_t a) {
    asm volatile("ldmatrix.sync.aligned.m8n8.x4.shared.b16 {%0,%1,%2,%3}, [%4];"
                 : "=r"(r0), "=r"(r1), "=r"(r2), "=r"(r3) : "r"(a));
}
__device__ __forceinline__ void ldsm_x4_t(uint32_t& r0, uint32_t& r1,
                                          uint32_t& r2, uint32_t& r3, uint32_t a) {
    asm volatile("ldmatrix.sync.aligned.m8n8.x4.trans.shared.b16 {%0,%1,%2,%3}, [%4];"
                 : "=r"(r0), "=r"(r1), "=r"(r2), "=r"(r3) : "r"(a));
}

__device__ __forceinline__ void mma_bf16(float* d, const uint32_t* a,
                                         const uint32_t* b) {
    asm volatile(
        "mma.sync.aligned.m16n8k16.row.col.f32.bf16.bf16.f32 "
        "{%0,%1,%2,%3}, {%4,%5,%6,%7}, {%8,%9}, {%0,%1,%2,%3};"
        : "+f"(d[0]), "+f"(d[1]), "+f"(d[2]), "+f"(d[3])
        : "r"(a[0]), "r"(a[1]), "r"(a[2]), "r"(a[3]), "r"(b[0]), "r"(b[1]));
}

__device__ __forceinline__ uint32_t bfpack(__nv_bfloat16 a, __nv_bfloat16 b) {
    return ((uint32_t)__bfloat16_as_ushort(b) << 16) | (uint32_t)__bfloat16_as_ushort(a);
}

// Pack (x,y) -> bf16x2 hi-plane + residual lo-plane (x in low half).
#define SPLITPK(dh, dl, x, y)                                                  \
    {                                                                          \
        float _x = (x), _y = (y);                                              \
        __nv_bfloat16 _hx = __float2bfloat16(_x), _hy = __float2bfloat16(_y);  \
        (dh) = bfpack(_hx, _hy);                                               \
        (dl) = bfpack(__float2bfloat16(_x - __bfloat162float(_hx)),            \
                      __float2bfloat16(_y - __bfloat162float(_hy)));           \
    }

// Swizzle inside a [rows x 32 bf16] tile (64B rows, 4 chunks)
__device__ __forceinline__ uint32_t swz(int row, int chunk) {
    return (uint32_t)(row * 64 + ((chunk ^ ((row >> 1) & 3)) << 4));
}
// Swizzle inside a [rows x 64 bf16] tile (128B rows, 8 chunks)
__device__ __forceinline__ uint32_t sw64o(int row, int chunk) {
    return (uint32_t)(row * 128 + ((chunk ^ (row & 7)) << 4));
}

// ---------------------------------------------------------------------------
// Conversion kernels
// ---------------------------------------------------------------------------
__global__ __launch_bounds__(256) void split_x_kernel(const float* __restrict__ X,
                                                      __nv_bfloat16* __restrict__ Y) {
    size_t t = (size_t)blockIdx.x * 256 + threadIdx.x;
    size_t e = t * 4;
    int row = (int)(e >> 10);
    int col = (int)(e & 1023);
    float4 v = *(const float4*)(X + e);
    float vv[4] = {v.x, v.y, v.z, v.w};
    __nv_bfloat16 h[4], l[4];
#pragma unroll
    for (int j = 0; j < 4; j++) {
        h[j] = __float2bfloat16(vv[j]);
        l[j] = __float2bfloat16(vv[j] - __bfloat162float(h[j]));
    }
    uint2 ph, pl;
    ph.x = bfpack(h[0], h[1]); ph.y = bfpack(h[2], h[3]);
    pl.x = bfpack(l[0], l[1]); pl.y = bfpack(l[2], l[3]);
    *(uint2*)(Y + (size_t)row * K2 + col)        = ph;
    *(uint2*)(Y + (size_t)row * K2 + 1024 + col) = pl;
}

__global__ __launch_bounds__(256) void wsplit_kernel(const float* __restrict__ W,
                                                     __nv_bfloat16* __restrict__ Y) {
    __shared__ float t[32][33];
    int k0 = blockIdx.x * 32, n0 = blockIdx.y * 32;
    int tx = threadIdx.x, ty = threadIdx.y;   // 32 x 8
#pragma unroll
    for (int i = 0; i < 4; i++)
        t[ty + 8 * i][tx] = W[(size_t)(k0 + ty + 8 * i) * 1024 + n0 + tx];
    __syncthreads();
#pragma unroll
    for (int i = 0; i < 4; i++) {
        int n = n0 + ty + 8 * i;
        float v = t[tx][ty + 8 * i];
        __nv_bfloat16 h = __float2bfloat16(v);
        __nv_bfloat16 l = __float2bfloat16(v - __bfloat162float(h));
        Y[(size_t)n * K2 + k0 + tx]        = h;
        Y[(size_t)n * K2 + 1024 + k0 + tx] = l;
    }
}

// ---------------------------------------------------------------------------
// bf16-split GEMM (3-term), all-planes-per-chunk variant.
// Per k-chunk of 32: load Ahi|Alo|Bhi|Blo tiles (8KB each), issue
// acc += Ahi*Bhi + Alo*Bhi + Ahi*Blo in-register. 32 iterations total.
// mode 0: fused QKV — epilogue routes to qs/ks/vs by 1024-col region,
//         applies region bias + scale, writes bf16 hi/lo split.
// mode 1: fp32 out Cf = A*B^T + bias0.
// ---------------------------------------------------------------------------
#define GSMEM (2 * 32768)

__global__ __launch_bounds__(256) void gemm3(
    const __nv_bfloat16* __restrict__ A2,
    const __nv_bfloat16* __restrict__ B2,
    const float* __restrict__ bias0,
    const float* __restrict__ bias1,
    const float* __restrict__ bias2,
    __nv_bfloat16* __restrict__ Cq,
    __nv_bfloat16* __restrict__ Ck,
    __nv_bfloat16* __restrict__ Cv,
    float* __restrict__ Cf,
    int mode, int N)
{
    extern __shared__ __align__(128) char smraw[];
    const uint32_t sm0 = smem_u32(smraw);

    const int tid  = threadIdx.x;
    const int lane = tid & 31;
    const int warp = tid >> 5;
    const int wm   = warp & 1;
    const int wn   = warp >> 1;
    const int brow = blockIdx.y * 128;
    const int bcol = blockIdx.x * 128;

    float acc[4][4][4];
#pragma unroll
    for (int i = 0; i < 4; i++)
#pragma unroll
        for (int j = 0; j < 4; j++)
#pragma unroll
            for (int e = 0; e < 4; e++) acc[i][j][e] = 0.f;

    const int r0 = tid >> 2,         c0 = tid & 3;
    const int r1 = (tid + 256) >> 2, c1 = (tid + 256) & 3;
    const uint32_t so0 = swz(r0, c0), so1 = swz(r1, c1);

    const int lrow  = lane & 15;
    const int lksel = lane >> 4;

#define ISSUE(it, stage)                                                       \
    do {                                                                       \
        int _kt = (it);                                                        \
        const __nv_bfloat16* _A = A2 + (size_t)brow * K2 + _kt * 32;           \
        const __nv_bfloat16* _B = B2 + (size_t)bcol * K2 + _kt * 32;           \
        uint32_t _s = sm0 + (stage) * 32768;                                   \
        cp_async16(_s + so0,          _A + (size_t)r0 * K2 + c0 * 8);          \
        cp_async16(_s + so1,          _A + (size_t)r1 * K2 + c1 * 8);          \
        cp_async16(_s + 8192  + so0,  _A + (size_t)r0 * K2 + 1024 + c0 * 8);   \
        cp_async16(_s + 8192  + so1,  _A + (size_t)r1 * K2 + 1024 + c1 * 8);   \
        cp_async16(_s + 16384 + so0,  _B + (size_t)r0 * K2 + c0 * 8);          \
        cp_async16(_s + 16384 + so1,  _B + (size_t)r1 * K2 + c1 * 8);          \
        cp_async16(_s + 24576 + so0,  _B + (size_t)r0 * K2 + 1024 + c0 * 8);   \
        cp_async16(_s + 24576 + so1,  _B + (size_t)r1 * K2 + 1024 + c1 * 8);   \
        cp_commit();                                                           \
    } while (0)

    ISSUE(0, 0);

    for (int it = 0; it < 32; it++) {
        const int cur = it & 1;
        if (it + 1 < 32) {
            ISSUE(it + 1, cur ^ 1);
            cp_wait<1>();
        } else {
            cp_wait<0>();
        }
        __syncthreads();

        const uint32_t sAh = sm0 + cur * 32768;
        const uint32_t sAl = sAh + 8192;
        const uint32_t sBh = sAh + 16384;
        const uint32_t sBl = sAh + 24576;

#pragma unroll
        for (int ks = 0; ks < 2; ks++) {
            const int chunk = ks * 2 + lksel;
            uint32_t ah[4][4], al[4][4], b[4][2];
#pragma unroll
            for (int mi = 0; mi < 4; mi++)
                ldsm_x4(ah[mi][0], ah[mi][1], ah[mi][2], ah[mi][3],
                        sAh + swz(wm * 64 + mi * 16 + lrow, chunk));
#pragma unroll
            for (int nj = 0; nj < 2; nj++) {
                uint32_t t0, t1, t2, t3;
                ldsm_x4(t0, t1, t2, t3,
                        sBh + swz(wn * 32 + nj * 16 + lrow, chunk));
                b[nj * 2 + 0][0] = t0;  b[nj * 2 + 1][0] = t1;
                b[nj * 2 + 0][1] = t2;  b[nj * 2 + 1][1] = t3;
            }
#pragma unroll
            for (int mi = 0; mi < 4; mi++)
#pragma unroll
                for (int ni = 0; ni < 4; ni++)
                    mma_bf16(acc[mi][ni], ah[mi], b[ni]);

#pragma unroll
            for (int mi = 0; mi < 4; mi++)
                ldsm_x4(al[mi][0], al[mi][1], al[mi][2], al[mi][3],
                        sAl + swz(wm * 64 + mi * 16 + lrow, chunk));
#pragma unroll
            for (int mi = 0; mi < 4; mi++)
#pragma unroll
                for (int ni = 0; ni < 4; ni++)
                    mma_bf16(acc[mi][ni], al[mi], b[ni]);

#pragma unroll
            for (int nj = 0; nj < 2; nj++) {
                uint32_t t0, t1, t2, t3;
                ldsm_x4(t0, t1, t2, t3,
                        sBl + swz(wn * 32 + nj * 16 + lrow, chunk));
                b[nj * 2 + 0][0] = t0;  b[nj * 2 + 1][0] = t1;
                b[nj * 2 + 0][1] = t2;  b[nj * 2 + 1][1] = t3;
            }
#pragma unroll
            for (int mi = 0; mi < 4; mi++)
#pragma unroll
                for (int ni = 0; ni < 4; ni++)
                    mma_bf16(acc[mi][ni], ah[mi], b[ni]);
        }
        __syncthreads();
    }
#undef ISSUE

    // ---- Epilogue ----
    if (mode == 0) {
        const int region = bcol >> 10;                  // 0:Q 1:K 2:V
        __nv_bfloat16* Cs  = (region == 0) ? Cq : (region == 1) ? Ck : Cv;
        const float*   bia = (region == 0) ? bias0 : (region == 1) ? bias1 : bias2;
        const float    scale = (region == 0) ? 0.125f : 1.0f;
        const int ncb = bcol & 1023;
#pragma unroll
        for (int mi = 0; mi < 4; mi++) {
#pragma unroll
            for (int ni = 0; ni < 4; ni++) {
                int r = brow + wm * 64 + mi * 16 + (lane >> 2);
                int c = ncb + wn * 32 + ni * 8 + (lane & 3) * 2;
                float bx = bia[c], by = bia[c + 1];
                float x0 = (acc[mi][ni][0] + bx) * scale;
                float x1 = (acc[mi][ni][1] + by) * scale;
                float x2 = (acc[mi][ni][2] + bx) * scale;
                float x3 = (acc[mi][ni][3] + by) * scale;
                uint32_t h01, l01, h23, l23;
                SPLITPK(h01, l01, x0, x1);
                SPLITPK(h23, l23, x2, x3);
                *(uint32_t*)(Cs + (size_t)r * K2 + c)              = h01;
                *(uint32_t*)(Cs + (size_t)r * K2 + 1024 + c)       = l01;
                *(uint32_t*)(Cs + (size_t)(r + 8) * K2 + c)        = h23;
                *(uint32_t*)(Cs + (size_t)(r + 8) * K2 + 1024 + c) = l23;
            }
        }
    } else {
#pragma unroll
        for (int mi = 0; mi < 4; mi++) {
#pragma unroll
            for (int ni = 0; ni < 4; ni++) {
                int r = brow + wm * 64 + mi * 16 + (lane >> 2);
                int c = bcol + wn * 32 + ni * 8 + (lane & 3) * 2;
                float bx = bias0[c], by = bias0[c + 1];
                *(float2*)(Cf + (size_t)r * N + c) =
                    make_float2(acc[mi][ni][0] + bx, acc[mi][ni][1] + by);
                *(float2*)(Cf + (size_t)(r + 8) * N + c) =
                    make_float2(acc[mi][ni][2] + bx, acc[mi][ni][3] + by);
            }
        }
    }
}

// ---------------------------------------------------------------------------
// Tensor-core flash attention (mma.sync bf16, 3-term split on both matmuls).
// CTA = 64 queries of one (b,h); 4 warps x 16 q-rows; 16 key-tiles of 64.
// ---------------------------------------------------------------------------
#define ATTN_SMEM (65536 + 512)

__global__ __launch_bounds__(128) void attn_mma(
    const __nv_bfloat16* __restrict__ Qs,
    const __nv_bfloat16* __restrict__ Ks,
    const __nv_bfloat16* __restrict__ Vsrc,
    const int* __restrict__ masks,
    __nv_bfloat16* __restrict__ Ob)
{
    extern __shared__ __align__(128) char smraw[];
    const uint32_t sb = smem_u32(smraw);
    int* mskp = (int*)(smraw + 65536);

    const int tid  = threadIdx.x;
    const int lane = tid & 31;
    const int warp = tid >> 5;
    const int lrow  = lane & 15;
    const int lksel = lane >> 4;
    const int b = blockIdx.z, h = blockIdx.y;
    const int q0 = blockIdx.x * 64;

    const __nv_bfloat16* Qg = Qs   + (size_t)(b * Sdim + q0) * K2 + h * 64;
    const __nv_bfloat16* Kg = Ks   + (size_t)(b * Sdim) * K2 + h * 64;
    const __nv_bfloat16* Vg = Vsrc + (size_t)(b * Sdim) * K2 + h * 64;

    // ---- stage Q (hi/lo) through smem, extract fragments into registers ----
#pragma unroll
    for (int i = 0; i < 4; i++) {
        int idx = tid + i * 128;
        int r = idx >> 3, c = idx & 7;
        uint32_t off = sw64o(r, c);
        cp_async16(sb + off,        Qg + (size_t)r * K2 + c * 8);
        cp_async16(sb + 8192 + off, Qg + (size_t)r * K2 + 1024 + c * 8);
    }
    cp_commit();
    cp_wait<0>();
    __syncthreads();

    uint32_t aqh[4][4], aql[4][4];
#pragma unroll
    for (int ks = 0; ks < 4; ks++) {
        uint32_t off = sw64o(warp * 16 + lrow, ks * 2 + lksel);
        ldsm_x4(aqh[ks][0], aqh[ks][1], aqh[ks][2], aqh[ks][3], sb + off);
        ldsm_x4(aql[ks][0], aql[ks][1], aql[ks][2], aql[ks][3], sb + 8192 + off);
    }
    __syncthreads();

#define AISSUE(kt, stg)                                                         \
    do {                                                                        \
        const __nv_bfloat16* _K = Kg + (size_t)(kt) * 64 * K2;                  \
        const __nv_bfloat16* _V = Vg + (size_t)(kt) * 64 * K2;                  \
        uint32_t _s = sb + (stg) * 32768;                                       \
        _Pragma("unroll")                                                       \
        for (int _i = 0; _i < 4; _i++) {                                        \
            int _idx = tid + _i * 128;                                          \
            int _r = _idx >> 3, _c = _idx & 7;                                  \
            uint32_t _o = sw64o(_r, _c);                                        \
            cp_async16(_s + _o,         _K + (size_t)_r * K2 + _c * 8);         \
            cp_async16(_s + 8192 + _o,  _K + (size_t)_r * K2 + 1024 + _c * 8);  \
            cp_async16(_s + 16384 + _o, _V + (size_t)_r * K2 + _c * 8);         \
            cp_async16(_s + 24576 + _o, _V + (size_t)_r * K2 + 1024 + _c * 8);  \
        }                                                                       \
        if (tid < 64) mskp[(stg) * 64 + tid] = masks[b * Sdim + (kt) * 64 + tid]; \
        cp_commit();                                                            \
    } while (0)

    float m0 = -1e30f, m1 = -1e30f, l0 = 0.f, l1 = 0.f;
    float o[8][4];
#pragma unroll
    for (int dt = 0; dt < 8; dt++)
#pragma unroll
        for (int e = 0; e < 4; e++) o[dt][e] = 0.f;

    AISSUE(0, 0);

    for (int kt = 0; kt < 16; kt++) {
        const int st = kt & 1;
        if (kt + 1 < 16) {
            AISSUE(kt + 1, st ^ 1);
            cp_wait<1>();
        } else {
            cp_wait<0>();
        }
        __syncthreads();

        const uint32_t sK  = sb + st * 32768;
        const uint32_t sKl = sK + 8192;
        const uint32_t sV  = sK + 16384;
        const uint32_t sVl = sK + 24576;
        const int* mk = mskp + st * 64;

        // -------- scores: S = Qhi*Khi + Qlo*Khi + Qhi*Klo --------
        float sc[8][4];
#pragma unroll
        for (int nt = 0; nt < 8; nt++)
#pragma unroll
            for (int e = 0; e < 4; e++) sc[nt][e] = 0.f;

#pragma unroll
        for (int ks = 0; ks < 4; ks++) {
            uint32_t bk[8][2];
#pragma unroll
            for (int np = 0; np < 4; np++) {
                uint32_t t0, t1, t2, t3;
                ldsm_x4(t0, t1, t2, t3, sK + sw64o(np * 16 + lrow, ks * 2 + lksel));
                bk[np * 2][0] = t0;  bk[np * 2][1] = t2;
                bk[np * 2 + 1][0] = t1;  bk[np * 2 + 1][1] = t3;
            }
#pragma unroll
            for (int nt = 0; nt < 8; nt++) mma_bf16(sc[nt], aqh[ks], bk[nt]);
#pragma unroll
            for (int nt = 0; nt < 8; nt++) mma_bf16(sc[nt], aql[ks], bk[nt]);
#pragma unroll
            for (int np = 0; np < 4; np++) {
                uint32_t t0, t1, t2, t3;
                ldsm_x4(t0, t1, t2, t3, sKl + sw64o(np * 16 + lrow, ks * 2 + lksel));
                bk[np * 2][0] = t0;  bk[np * 2][1] = t2;
                bk[np * 2 + 1][0] = t1;  bk[np * 2 + 1][1] = t3;
            }
#pragma unroll
            for (int nt = 0; nt < 8; nt++) mma_bf16(sc[nt], aqh[ks], bk[nt]);
        }

        // -------- mask --------
#pragma unroll
        for (int nt = 0; nt < 8; nt++) {
            int k0 = nt * 8 + 2 * (lane & 3);
            if (mk[k0] == 0)     { sc[nt][0] = -1e9f; sc[nt][2] = -1e9f; }
            if (mk[k0 + 1] == 0) { sc[nt][1] = -1e9f; sc[nt][3] = -1e9f; }
        }

        // -------- online softmax (rows r = lane>>2 and r+8) --------
        float mx0 = -1e30f, mx1 = -1e30f;
#pragma unroll
        for (int nt = 0; nt < 8; nt++) {
            mx0 = fmaxf(mx0, fmaxf(sc[nt][0], sc[nt][1]));
            mx1 = fmaxf(mx1, fmaxf(sc[nt][2], sc[nt][3]));
        }
        mx0 = fmaxf(mx0, __shfl_xor_sync(0xffffffffu, mx0, 1));
        mx0 = fmaxf(mx0, __shfl_xor_sync(0xffffffffu, mx0, 2));
        mx1 = fmaxf(mx1, __shfl_xor_sync(0xffffffffu, mx1, 1));
        mx1 = fmaxf(mx1, __shfl_xor_sync(0xffffffffu, mx1, 2));

        float nm0 = fmaxf(m0, mx0), nm1 = fmaxf(m1, mx1);
        float cr0 = __expf(m0 - nm0), cr1 = __expf(m1 - nm1);
        float s0 = 0.f, s1 = 0.f;
#pragma unroll
        for (int nt = 0; nt < 8; nt++) {
            sc[nt][0] = __expf(sc[nt][0] - nm0);  s0 += sc[nt][0];
            sc[nt][1] = __expf(sc[nt][1] - nm0);  s0 += sc[nt][1];
            sc[nt][2] = __expf(sc[nt][2] - nm1);  s1 += sc[nt][2];
            sc[nt][3] = __expf(sc[nt][3] - nm1);  s1 += sc[nt][3];
        }
        s0 += __shfl_xor_sync(0xffffffffu, s0, 1);
        s0 += __shfl_xor_sync(0xffffffffu, s0, 2);
        s1 += __shfl_xor_sync(0xffffffffu, s1, 1);
        s1 += __shfl_xor_sync(0xffffffffu, s1, 2);
        l0 = l0 * cr0 + s0;  l1 = l1 * cr1 + s1;
        m0 = nm0;  m1 = nm1;
#pragma unroll
        for (int dt = 0; dt < 8; dt++) {
            o[dt][0] *= cr0;  o[dt][1] *= cr0;
            o[dt][2] *= cr1;  o[dt][3] *= cr1;
        }

        // -------- O += Phi*Vhi + Plo*Vhi + Phi*Vlo --------
#pragma unroll
        for (int ks = 0; ks < 4; ks++) {
            uint32_t ah[4], al[4];
            SPLITPK(ah[0], al[0], sc[2 * ks][0],     sc[2 * ks][1]);
            SPLITPK(ah[1], al[1], sc[2 * ks][2],     sc[2 * ks][3]);
            SPLITPK(ah[2], al[2], sc[2 * ks + 1][0], sc[2 * ks + 1][1]);
            SPLITPK(ah[3], al[3], sc[2 * ks + 1][2], sc[2 * ks + 1][3]);

            uint32_t bv[8][2];
#pragma unroll
            for (int dp = 0; dp < 4; dp++) {
                uint32_t t0, t1, t2, t3;
                ldsm_x4_t(t0, t1, t2, t3, sV + sw64o(ks * 16 + lrow, dp * 2 + lksel));
                bv[dp * 2][0] = t0;  bv[dp * 2][1] = t1;
                bv[dp * 2 + 1][0] = t2;  bv[dp * 2 + 1][1] = t3;
            }
#pragma unroll
            for (int dt = 0; dt < 8; dt++) mma_bf16(o[dt], ah, bv[dt]);
#pragma unroll
            for (int dt = 0; dt < 8; dt++) mma_bf16(o[dt], al, bv[dt]);
#pragma unroll
            for (int dp = 0; dp < 4; dp++) {
                uint32_t t0, t1, t2, t3;
                ldsm_x4_t(t0, t1, t2, t3, sVl + sw64o(ks * 16 + lrow, dp * 2 + lksel));
                bv[dp * 2][0] = t0;  bv[dp * 2][1] = t1;
                bv[dp * 2 + 1][0] = t2;  bv[dp * 2 + 1][1] = t3;
            }
#pragma unroll
            for (int dt = 0; dt < 8; dt++) mma_bf16(o[dt], ah, bv[dt]);
        }
        __syncthreads();
    }
#undef AISSUE

    // -------- normalize + write bf16 hi/lo split --------
    float i0 = 1.f / l0, i1 = 1.f / l1;
    int rg = b * Sdim + q0 + warp * 16 + (lane >> 2);
    int cb = h * 64 + 2 * (lane & 3);
    __nv_bfloat16* O0 = Ob + (size_t)rg * K2;
    __nv_bfloat16* O1 = Ob + (size_t)(rg + 8) * K2;
#pragma unroll
    for (int dt = 0; dt < 8; dt++) {
        int c = cb + dt * 8;
        uint32_t h01, l01, h23, l23;
        SPLITPK(h01, l01, o[dt][0] * i0, o[dt][1] * i0);
        SPLITPK(h23, l23, o[dt][2] * i1, o[dt][3] * i1);
        *(uint32_t*)(O0 + c)        = h01;
        *(uint32_t*)(O0 + 1024 + c) = l01;
        *(uint32_t*)(O1 + c)        = h23;
        *(uint32_t*)(O1 + 1024 + c) = l23;
    }
}

// ---------------------------------------------------------------------------
// kernel_launch: graph-capturable, allocation-free.
// Input order: x, masks, Wq, bq, Wk, bk, Wv, bv, Wo, bo
// ---------------------------------------------------------------------------
extern "C" void kernel_launch(void* const* d_in, const int* in_sizes, int n_in,
                              void* d_out, int out_size)
{
    const float* x     = (const float*)d_in[0];
    const int*   masks = (const int*)  d_in[1];
    const float* Wq    = (const float*)d_in[2];
    const float* bq    = (const float*)d_in[3];
    const float* Wk    = (const float*)d_in[4];
    const float* bk    = (const float*)d_in[5];
    const float* Wv    = (const float*)d_in[6];
    const float* bv    = (const float*)d_in[7];
    const float* Wo    = (const float*)d_in[8];
    const float* bo    = (const float*)d_in[9];
    float* out = (float*)d_out;

    __nv_bfloat16 *xs, *wqkv, *wo2, *qs, *ks, *vs, *attb;
    cudaGetSymbolAddress((void**)&xs,   g_xs);
    cudaGetSymbolAddress((void**)&wqkv, g_wqkv);
    cudaGetSymbolAddress((void**)&wo2,  g_wo);
    cudaGetSymbolAddress((void**)&qs,   g_qs);
    cudaGetSymbolAddress((void**)&ks,   g_ks);
    cudaGetSymbolAddress((void**)&vs,   g_vs);
    cudaGetSymbolAddress((void**)&attb, g_attb);

    cudaFuncSetAttribute(gemm3,    cudaFuncAttributeMaxDynamicSharedMemorySize, GSMEM);
    cudaFuncSetAttribute(attn_mma, cudaFuncAttributeMaxDynamicSharedMemorySize, ATTN_SMEM);

    // fp32 -> bf16 hi/lo conversions (weights concat into g_wqkv)
    split_x_kernel<<<(Mdim * Ddim) / 4 / 256, 256>>>(x, xs);
    dim3 wgrid(32, 32), wblk(32, 8);
    wsplit_kernel<<<wgrid, wblk>>>(Wq, wqkv);
    wsplit_kernel<<<wgrid, wblk>>>(Wk, wqkv + (size_t)Ddim * K2);
    wsplit_kernel<<<wgrid, wblk>>>(Wv, wqkv + (size_t)2 * Ddim * K2);
    wsplit_kernel<<<wgrid, wblk>>>(Wo, wo2);

    // Fused QKV projection -> bf16 split outputs (Q pre-scaled by 1/8)
    dim3 gq(3 * Ddim / 128, Mdim / 128);   // (24, 64)
    gemm3<<<gq, 256, GSMEM>>>(xs, wqkv, bq, bk, bv, qs, ks, vs, nullptr, 0, Ddim);

    // Tensor-core flash attention -> bf16 split
    dim3 ga(Sdim / 64, Hdim, Bdim);        // (16, 16, 8)
    attn_mma<<<ga, 128, ATTN_SMEM>>>(qs, ks, vs, masks, attb);

    // Output projection -> fp32
    dim3 go(Ddim / 128, Mdim / 128);       // (8, 64)
    gemm3<<<go, 256, GSMEM>>>(attb, wo2, bo, nullptr, nullptr, nullptr, nullptr,
                              nullptr, out, 1, Ddim);
}